// round 2
// baseline (speedup 1.0000x reference)
#include <cuda_runtime.h>
#include <cuda_bf16.h>

#define L2D 147456   // 384*384
#define IMG 384
#define NPIX_INV (1.0/147456.0)

// ---------------- static scratch (no allocations allowed) ----------------
__device__ float g_x1n[788*384];
__device__ float g_row[64*384];
__device__ float g_col[64*384];
__device__ float g_Ag[64*384];
__device__ float g_Bg[64*384];
__device__ float g_W2s[64*210];
__device__ float g_c2[64];
__device__ double g_x2s[210];
__device__ double g_x2q[210];
__device__ double g_statS[16*64];
__device__ double g_statQ[16*64];
__device__ float g_nsc[16*64];
__device__ float g_nsh[16*64];

__device__ float g_bufP[64*L2D]; // pair2 raw, later ping-pong buffer
__device__ float g_bufR[64*L2D]; // raw (pre-norm) buffer
__device__ float g_bufX[64*L2D];
__device__ float g_bufT[64*L2D];

// ---------------- helpers ----------------
__device__ __forceinline__ void blockReduce2(float& s, float& q, float* sm) {
    __syncthreads();            // protect smem reuse across calls
    int lane = threadIdx.x & 31, w = threadIdx.x >> 5;
    #pragma unroll
    for (int o = 16; o; o >>= 1) {
        s += __shfl_down_sync(0xffffffffu, s, o);
        q += __shfl_down_sync(0xffffffffu, q, o);
    }
    if (lane == 0) { sm[2*w] = s; sm[2*w+1] = q; }
    __syncthreads();
    int nw = blockDim.x >> 5;
    if (threadIdx.x == 0) {
        float S = 0.f, Q = 0.f;
        for (int i = 0; i < nw; i++) { S += sm[2*i]; Q += sm[2*i+1]; }
        sm[0] = S; sm[1] = Q;
    }
    __syncthreads();
    s = sm[0]; q = sm[1];
}

__device__ __forceinline__ float lrelu(float v) { return v < 0.f ? 0.01f*v : v; }

// ---------------- zero stats ----------------
__global__ void k_zero() {
    int t = blockIdx.x*256 + threadIdx.x;
    if (t < 16*64) { g_statS[t] = 0.0; g_statQ[t] = 0.0; }
    if (t < 210)   { g_x2s[t] = 0.0;  g_x2q[t] = 0.0; }
}

// ---------------- x_1d instance norm (per channel over L=384) ----------------
__global__ void k1_norm1d(const float* __restrict__ x) {
    __shared__ float sm[32];
    int d = blockIdx.x;
    float v = x[d*384 + threadIdx.x];
    float s = v, q = v*v;
    blockReduce2(s, q, sm);
    float mu = s * (1.f/384.f);
    float var = q * (1.f/384.f) - mu*mu;
    float iv = rsqrtf(var + 1e-5f);
    g_x1n[d*384 + threadIdx.x] = (v - mu) * iv;
}

// ---------------- x_2d per-channel stats ----------------
__global__ void k2_x2stats(const float* __restrict__ x2) {
    __shared__ float sm[32];
    int c = blockIdx.y;
    int base = c*L2D + blockIdx.x*4096 + threadIdx.x;
    float s = 0.f, q = 0.f;
    #pragma unroll
    for (int k = 0; k < 16; k++) { float v = x2[base + k*256]; s += v; q += v*v; }
    blockReduce2(s, q, sm);
    if (threadIdx.x == 0) {
        atomicAdd(&g_x2s[c], (double)s);
        atomicAdd(&g_x2q[c], (double)q);
    }
}

// ---------------- fold x2 norm into W2 ----------------
__global__ void k2b_scaleW2(const float* __restrict__ W2) {
    __shared__ float smu[210], siv[210];
    int t = threadIdx.x;
    if (t < 210) {
        float mu = (float)(g_x2s[t] * NPIX_INV);
        float var = (float)(g_x2q[t] * NPIX_INV) - mu*mu;
        smu[t] = mu; siv[t] = rsqrtf(var + 1e-5f);
    }
    __syncthreads();
    for (int i = t; i < 64*210; i += blockDim.x) g_W2s[i] = W2[i] * siv[i % 210];
    if (t < 64) {
        float a = 0.f;
        for (int d = 0; d < 210; d++) a += W2[t*210+d] * smu[d] * siv[d];
        g_c2[t] = -a;
    }
}

// ---------------- row/col projections ----------------
__global__ void k3_rowcol(const float* __restrict__ W1) {
    int c = blockIdx.x >> 1, which = blockIdx.x & 1;
    const float* w = W1 + c*1576 + which*788;
    int l = threadIdx.x;
    float acc = 0.f;
    #pragma unroll 4
    for (int d = 0; d < 788; d++) acc += w[d] * g_x1n[d*384 + l];
    (which ? g_col : g_row)[c*384 + l] = acc;
}

// ---------------- pair1 stats (separable!) + precompute A/B ----------------
__global__ void k3b_pair1(const float* __restrict__ g1, const float* __restrict__ b1) {
    __shared__ float sm[32];
    int c = blockIdx.x, t = threadIdx.x; // 128 threads
    float sr = 0.f, qr = 0.f, sc_ = 0.f, qc = 0.f;
    for (int i = t; i < 384; i += 128) {
        float r = g_row[c*384+i]; sr += r; qr += r*r;
        float cl = g_col[c*384+i]; sc_ += cl; qc += cl*cl;
    }
    blockReduce2(sr, qr, sm);
    blockReduce2(sc_, qc, sm);
    float mur = sr*(1.f/384.f), muc = sc_*(1.f/384.f);
    float var = (qr*(1.f/384.f) - mur*mur) + (qc*(1.f/384.f) - muc*muc);
    float iv = rsqrtf(var + 1e-5f);
    float mu = mur + muc;
    float gc = g1[c], bc = b1[c];
    for (int i = t; i < 384; i += 128) {
        g_Ag[c*384+i] = gc*iv*(g_row[c*384+i] - mu) + bc;
        g_Bg[c*384+i] = gc*iv*g_col[c*384+i];
    }
}

// ---------------- pair2 = W2s @ x2 + c2, with stats (idx 0) ----------------
__global__ void __launch_bounds__(256) k4_pair2(const float* __restrict__ x2) {
    __shared__ float s_w[32*210];
    __shared__ float s_red[8*32*2];
    int tid = threadIdx.x;
    int base = blockIdx.x * 512;
    int cb = blockIdx.y * 32;
    for (int i = tid; i < 32*210; i += 256) s_w[i] = g_W2s[cb*210 + i];
    __syncthreads();
    float a0[32], a1[32];
    #pragma unroll
    for (int i = 0; i < 32; i++) { a0[i] = 0.f; a1[i] = 0.f; }
    #pragma unroll 1
    for (int d = 0; d < 210; d++) {
        float v0 = x2[d*L2D + base + tid];
        float v1 = x2[d*L2D + base + tid + 256];
        #pragma unroll
        for (int co = 0; co < 32; co++) {
            float w = s_w[co*210 + d];
            a0[co] += w*v0; a1[co] += w*v1;
        }
    }
    int lane = tid & 31, w = tid >> 5;
    #pragma unroll
    for (int co = 0; co < 32; co++) {
        float cc = g_c2[cb+co];
        float v0 = a0[co] + cc, v1 = a1[co] + cc;
        g_bufP[(cb+co)*L2D + base + tid]       = v0;
        g_bufP[(cb+co)*L2D + base + tid + 256] = v1;
        float s = v0 + v1, q = v0*v0 + v1*v1;
        #pragma unroll
        for (int o = 16; o; o >>= 1) {
            s += __shfl_down_sync(0xffffffffu, s, o);
            q += __shfl_down_sync(0xffffffffu, q, o);
        }
        if (lane == 0) { s_red[(w*32+co)*2] = s; s_red[(w*32+co)*2+1] = q; }
    }
    __syncthreads();
    if (tid < 32) {
        float s = 0.f, q = 0.f;
        for (int i = 0; i < 8; i++) { s += s_red[(i*32+tid)*2]; q += s_red[(i*32+tid)*2+1]; }
        atomicAdd(&g_statS[cb+tid], (double)s);
        atomicAdd(&g_statQ[cb+tid], (double)q);
    }
}

// ---------------- finalize stats -> per-channel scale/shift ----------------
__global__ void k_fin(int idx, const float* __restrict__ g, const float* __restrict__ b) {
    int c = threadIdx.x; // 64
    float mu = (float)(g_statS[idx*64+c] * NPIX_INV);
    float var = (float)(g_statQ[idx*64+c] * NPIX_INV) - mu*mu;
    float iv = rsqrtf(var + 1e-5f);
    g_nsc[idx*64+c] = g[c]*iv;
    g_nsh[idx*64+c] = b[c] - g[c]*iv*mu;
}

// ---------------- pair = W3a@p1n + W3b@p2n, with stats (idx 1) ----------------
__global__ void __launch_bounds__(256) k5_mix(const float* __restrict__ W3) {
    __shared__ float s_w3[64*128];
    __shared__ float s_red[8*64*2];
    __shared__ float s_a[64], s_b[64];
    int tid = threadIdx.x;
    for (int i = tid; i < 64*128; i += 256) s_w3[i] = W3[i];
    if (tid < 64) { s_a[tid] = g_nsc[tid]; s_b[tid] = g_nsh[tid]; }  // idx 0
    __syncthreads();
    int pix = blockIdx.x*256 + tid;
    int i = pix / 384, j = pix - i*384;
    float acc[64];
    #pragma unroll
    for (int c = 0; c < 64; c++) acc[c] = 0.f;
    #pragma unroll 1
    for (int c = 0; c < 64; c++) {
        float p2 = g_bufP[c*L2D + pix];
        p2 = lrelu(s_a[c]*p2 + s_b[c]);
        float p1 = lrelu(g_Ag[c*384+i] + g_Bg[c*384+j]);
        #pragma unroll
        for (int co = 0; co < 64; co++)
            acc[co] += s_w3[co*128 + c]*p1 + s_w3[co*128 + 64 + c]*p2;
    }
    int lane = tid & 31, w = tid >> 5;
    #pragma unroll
    for (int co = 0; co < 64; co++) {
        float v = acc[co];
        g_bufR[co*L2D + pix] = v;
        float s = v, q = v*v;
        #pragma unroll
        for (int o = 16; o; o >>= 1) {
            s += __shfl_down_sync(0xffffffffu, s, o);
            q += __shfl_down_sync(0xffffffffu, q, o);
        }
        if (lane == 0) { s_red[(w*64+co)*2] = s; s_red[(w*64+co)*2+1] = q; }
    }
    __syncthreads();
    if (tid < 64) {
        float s = 0.f, q = 0.f;
        for (int k = 0; k < 8; k++) { s += s_red[(k*64+tid)*2]; q += s_red[(k*64+tid)*2+1]; }
        atomicAdd(&g_statS[64+tid], (double)s);
        atomicAdd(&g_statQ[64+tid], (double)q);
    }
}

// ---------------- normalize + leaky (+ residual) ----------------
__global__ void k_apply(const float* __restrict__ raw, int idx,
                        const float* __restrict__ res, float* __restrict__ out) {
    int i = blockIdx.x*256 + threadIdx.x;
    int c = i / L2D;
    float v = raw[i]*g_nsc[idx*64+c] + g_nsh[idx*64+c];
    v = lrelu(v);
    if (res) v += res[i];
    out[i] = v;
}

// ---------------- dilated 3x3 conv + bias + stats ----------------
template<int D>
__global__ void __launch_bounds__(256) conv_kernel(
    const float* __restrict__ in, const float* __restrict__ w,
    const float* __restrict__ bias, int statIdx, float* __restrict__ out)
{
    constexpr int SH = 8 + 2*D, SW = 64 + 2*D;
    __shared__ float s_w[16*64*9];
    __shared__ float s_in[SH*SW];
    __shared__ float s_red[8*16*2];
    int tid = threadIdx.x;
    int tileX = blockIdx.x * 64;
    int tileY = blockIdx.y * 8;
    int cobase = blockIdx.z * 16;
    const float* wg = w + cobase*64*9;
    for (int i = tid; i < 16*64*9; i += 256) s_w[i] = wg[i];
    int r0 = tid >> 6, x0 = tid & 63;
    float a0[16], a1[16];
    #pragma unroll
    for (int i = 0; i < 16; i++) { a0[i] = 0.f; a1[i] = 0.f; }

    #pragma unroll 1
    for (int ci = 0; ci < 64; ci++) {
        __syncthreads();
        const float* inc = in + ci*L2D;
        for (int i = tid; i < SH*SW; i += 256) {
            int sr = i / SW, sc = i - sr*SW;
            int gy = tileY + sr - D, gx = tileX + sc - D;
            float v = 0.f;
            if (gy >= 0 && gy < IMG && gx >= 0 && gx < IMG) v = inc[gy*IMG + gx];
            s_in[i] = v;
        }
        __syncthreads();
        float t0[9], t1[9];
        #pragma unroll
        for (int kr = 0; kr < 3; kr++)
            #pragma unroll
            for (int kc = 0; kc < 3; kc++) {
                t0[kr*3+kc] = s_in[(r0   + kr*D)*SW + x0 + kc*D];
                t1[kr*3+kc] = s_in[(r0+4 + kr*D)*SW + x0 + kc*D];
            }
        #pragma unroll
        for (int t = 0; t < 9; t++) {
            float v0 = t0[t], v1 = t1[t];
            #pragma unroll
            for (int co = 0; co < 16; co++) {
                float wv = s_w[(co*64 + ci)*9 + t];
                a0[co] += v0*wv;
                a1[co] += v1*wv;
            }
        }
    }

    int gy0 = tileY + r0, gy1 = gy0 + 4, gx = tileX + x0;
    int lane = tid & 31, wrp = tid >> 5;
    #pragma unroll
    for (int co = 0; co < 16; co++) {
        float b = bias[cobase+co];
        float v0 = a0[co] + b, v1 = a1[co] + b;
        out[(cobase+co)*L2D + gy0*IMG + gx] = v0;
        out[(cobase+co)*L2D + gy1*IMG + gx] = v1;
        float s = v0 + v1, q = v0*v0 + v1*v1;
        #pragma unroll
        for (int o = 16; o; o >>= 1) {
            s += __shfl_down_sync(0xffffffffu, s, o);
            q += __shfl_down_sync(0xffffffffu, q, o);
        }
        if (lane == 0) { s_red[(wrp*16+co)*2] = s; s_red[(wrp*16+co)*2+1] = q; }
    }
    __syncthreads();
    if (tid < 16) {
        float s = 0.f, q = 0.f;
        for (int i = 0; i < 8; i++) { s += s_red[(i*16+tid)*2]; q += s_red[(i*16+tid)*2+1]; }
        atomicAdd(&g_statS[statIdx*64 + cobase + tid], (double)s);
        atomicAdd(&g_statQ[statIdx*64 + cobase + tid], (double)q);
    }
}

// ---------------- launch ----------------
extern "C" void kernel_launch(void* const* d_in, const int* in_sizes, int n_in,
                              void* d_out, int out_size) {
    const float* x1d  = (const float*)d_in[0];
    const float* x2   = (const float*)d_in[1];
    const float* W1   = (const float*)d_in[2];
    const float* g1   = (const float*)d_in[3];
    const float* b1   = (const float*)d_in[4];
    const float* W2   = (const float*)d_in[5];
    const float* g2   = (const float*)d_in[6];
    const float* b2   = (const float*)d_in[7];
    const float* W3   = (const float*)d_in[8];
    const float* g3   = (const float*)d_in[9];
    const float* b3   = (const float*)d_in[10];
    const float* rw   = (const float*)d_in[11];
    const float* rb   = (const float*)d_in[12];
    const float* rg   = (const float*)d_in[13];
    const float* rbe  = (const float*)d_in[14];
    float* out = (float*)d_out;

    float *bP, *bR, *bX, *bT;
    cudaGetSymbolAddress((void**)&bP, g_bufP);
    cudaGetSymbolAddress((void**)&bR, g_bufR);
    cudaGetSymbolAddress((void**)&bX, g_bufX);
    cudaGetSymbolAddress((void**)&bT, g_bufT);

    k_zero<<<4, 256>>>();
    k1_norm1d<<<788, 384>>>(x1d);
    k2_x2stats<<<dim3(36, 210), 256>>>(x2);
    k2b_scaleW2<<<1, 256>>>(W2);
    k3_rowcol<<<128, 384>>>(W1);
    k3b_pair1<<<64, 128>>>(g1, b1);
    k4_pair2<<<dim3(288, 2), 256>>>(x2);
    k_fin<<<1, 64>>>(0, g2, b2);
    k5_mix<<<576, 256>>>(W3);
    k_fin<<<1, 64>>>(1, g3, b3);
    k_apply<<<36864, 256>>>(bR, 1, nullptr, bX);

    float* cur = bX;
    float* other = bP;
    const int DIL[5] = {1, 2, 4, 2, 1};
    for (int l = 0; l < 5; l++) {
        for (int k = 0; k < 2; k++) {
            int si = 2 + l*2 + k;
            const float* wk  = rw  + (l*2+k)*36864;
            const float* bk  = rb  + (l*2+k)*64;
            const float* gk  = rg  + (l*2+k)*64;
            const float* bbk = rbe + (l*2+k)*64;
            const float* src = (k == 0) ? cur : bT;
            dim3 grid(6, 48, 4);
            switch (DIL[l]) {
                case 1: conv_kernel<1><<<grid, 256>>>(src, wk, bk, si, bR); break;
                case 2: conv_kernel<2><<<grid, 256>>>(src, wk, bk, si, bR); break;
                case 4: conv_kernel<4><<<grid, 256>>>(src, wk, bk, si, bR); break;
            }
            k_fin<<<1, 64>>>(si, gk, bbk);
            if (k == 0) {
                k_apply<<<36864, 256>>>(bR, si, nullptr, bT);
            } else {
                float* dst = (l == 4) ? out : other;
                k_apply<<<36864, 256>>>(bR, si, cur, dst);
                if (l < 4) { float* tmp = cur; cur = other; other = tmp; }
            }
        }
    }
}

// round 7
// speedup vs baseline: 1.4732x; 1.4732x over previous
#include <cuda_runtime.h>
#include <cuda_bf16.h>
#include <cstdint>

#define L2D 147456   // 384*384
#define IMG 384
#define NPIX_INV (1.0/147456.0)

// ---------------- static scratch ----------------
__device__ float g_x1n[788*384];
__device__ float g_row[64*384];
__device__ float g_col[64*384];
__device__ float g_Ag[64*384];
__device__ float g_Bg[64*384];
__device__ float g_W2s[64*210];
__device__ float g_c2[64];
__device__ double g_x2s[210];
__device__ double g_x2q[210];
__device__ double g_statS[16*64];
__device__ double g_statQ[16*64];
__device__ float g_nsc[16*64];
__device__ float g_nsh[16*64];

__device__ float g_wsw[10*576*64];   // tf32-rounded weights, [l2k][k=tap*64+ci][co]

__device__ float g_bufP[64*L2D];
__device__ float g_bufR[64*L2D];
__device__ float g_bufX[64*L2D];
__device__ float g_bufT[64*L2D];

// ---------------- helpers ----------------
__device__ __forceinline__ uint32_t cvt_tf32(float v){
    uint32_t u; asm("cvt.rna.tf32.f32 %0, %1;" : "=r"(u) : "f"(v)); return u;
}

__device__ __forceinline__ void mma_tf32_16n8k8(float* c, const uint32_t* a, const uint32_t* b){
    asm volatile("mma.sync.aligned.m16n8k8.row.col.f32.tf32.tf32.f32 "
        "{%0,%1,%2,%3}, {%4,%5,%6,%7}, {%8,%9}, {%0,%1,%2,%3};"
        : "+f"(c[0]), "+f"(c[1]), "+f"(c[2]), "+f"(c[3])
        : "r"(a[0]), "r"(a[1]), "r"(a[2]), "r"(a[3]), "r"(b[0]), "r"(b[1]));
}

__device__ __forceinline__ void blockReduce2(float& s, float& q, float* sm) {
    __syncthreads();
    int lane = threadIdx.x & 31, w = threadIdx.x >> 5;
    #pragma unroll
    for (int o = 16; o; o >>= 1) {
        s += __shfl_down_sync(0xffffffffu, s, o);
        q += __shfl_down_sync(0xffffffffu, q, o);
    }
    if (lane == 0) { sm[2*w] = s; sm[2*w+1] = q; }
    __syncthreads();
    int nw = blockDim.x >> 5;
    if (threadIdx.x == 0) {
        float S = 0.f, Q = 0.f;
        for (int i = 0; i < nw; i++) { S += sm[2*i]; Q += sm[2*i+1]; }
        sm[0] = S; sm[1] = Q;
    }
    __syncthreads();
    s = sm[0]; q = sm[1];
}

__device__ __forceinline__ float lrelu(float v) { return v < 0.f ? 0.01f*v : v; }

// ---------------- zero stats ----------------
__global__ void k_zero() {
    int t = blockIdx.x*256 + threadIdx.x;
    if (t < 16*64) { g_statS[t] = 0.0; g_statQ[t] = 0.0; }
    if (t < 210)   { g_x2s[t] = 0.0;  g_x2q[t] = 0.0; }
}

// ---------------- weight prep: tf32 round, reorder to [l2k][k][co] ----------------
__global__ void k_wprep(const float* __restrict__ rw) {
    int i = blockIdx.x*256 + threadIdx.x;
    if (i >= 10*64*64*9) return;
    int tap = i % 9; int r = i / 9;
    int ci = r & 63; r >>= 6;
    int co = r & 63; int l2k = r >> 6;
    g_wsw[l2k*36864 + (tap*64 + ci)*64 + co] = __uint_as_float(cvt_tf32(rw[i]));
}

// ---------------- x_1d instance norm ----------------
__global__ void k1_norm1d(const float* __restrict__ x) {
    __shared__ float sm[32];
    int d = blockIdx.x;
    float v = x[d*384 + threadIdx.x];
    float s = v, q = v*v;
    blockReduce2(s, q, sm);
    float mu = s * (1.f/384.f);
    float var = q * (1.f/384.f) - mu*mu;
    float iv = rsqrtf(var + 1e-5f);
    g_x1n[d*384 + threadIdx.x] = (v - mu) * iv;
}

// ---------------- x_2d per-channel stats ----------------
__global__ void k2_x2stats(const float* __restrict__ x2) {
    __shared__ float sm[32];
    int c = blockIdx.y;
    int base = c*L2D + blockIdx.x*4096 + threadIdx.x;
    float s = 0.f, q = 0.f;
    #pragma unroll
    for (int k = 0; k < 16; k++) { float v = x2[base + k*256]; s += v; q += v*v; }
    blockReduce2(s, q, sm);
    if (threadIdx.x == 0) {
        atomicAdd(&g_x2s[c], (double)s);
        atomicAdd(&g_x2q[c], (double)q);
    }
}

// ---------------- fold x2 norm into W2 ----------------
__global__ void k2b_scaleW2(const float* __restrict__ W2) {
    __shared__ float smu[210], siv[210];
    int t = threadIdx.x;
    if (t < 210) {
        float mu = (float)(g_x2s[t] * NPIX_INV);
        float var = (float)(g_x2q[t] * NPIX_INV) - mu*mu;
        smu[t] = mu; siv[t] = rsqrtf(var + 1e-5f);
    }
    __syncthreads();
    for (int i = t; i < 64*210; i += blockDim.x) g_W2s[i] = W2[i] * siv[i % 210];
    if (t < 64) {
        float a = 0.f;
        for (int d = 0; d < 210; d++) a += W2[t*210+d] * smu[d] * siv[d];
        g_c2[t] = -a;
    }
}

// ---------------- row/col projections ----------------
__global__ void k3_rowcol(const float* __restrict__ W1) {
    int c = blockIdx.x >> 1, which = blockIdx.x & 1;
    const float* w = W1 + c*1576 + which*788;
    int l = threadIdx.x;
    float acc = 0.f;
    #pragma unroll 4
    for (int d = 0; d < 788; d++) acc += w[d] * g_x1n[d*384 + l];
    (which ? g_col : g_row)[c*384 + l] = acc;
}

// ---------------- pair1 separable stats ----------------
__global__ void k3b_pair1(const float* __restrict__ g1, const float* __restrict__ b1) {
    __shared__ float sm[32];
    int c = blockIdx.x, t = threadIdx.x;
    float sr = 0.f, qr = 0.f, sc_ = 0.f, qc = 0.f;
    for (int i = t; i < 384; i += 128) {
        float r = g_row[c*384+i]; sr += r; qr += r*r;
        float cl = g_col[c*384+i]; sc_ += cl; qc += cl*cl;
    }
    blockReduce2(sr, qr, sm);
    blockReduce2(sc_, qc, sm);
    float mur = sr*(1.f/384.f), muc = sc_*(1.f/384.f);
    float var = (qr*(1.f/384.f) - mur*mur) + (qc*(1.f/384.f) - muc*muc);
    float iv = rsqrtf(var + 1e-5f);
    float mu = mur + muc;
    float gc = g1[c], bc = b1[c];
    for (int i = t; i < 384; i += 128) {
        g_Ag[c*384+i] = gc*iv*(g_row[c*384+i] - mu) + bc;
        g_Bg[c*384+i] = gc*iv*g_col[c*384+i];
    }
}

// ---------------- pair2 = W2s @ x2 + c2 (stats idx 0) ----------------
__global__ void __launch_bounds__(256) k4_pair2(const float* __restrict__ x2) {
    __shared__ float s_w[32*210];
    __shared__ float s_red[8*32*2];
    int tid = threadIdx.x;
    int base = blockIdx.x * 512;
    int cb = blockIdx.y * 32;
    for (int i = tid; i < 32*210; i += 256) s_w[i] = g_W2s[cb*210 + i];
    __syncthreads();
    float a0[32], a1[32];
    #pragma unroll
    for (int i = 0; i < 32; i++) { a0[i] = 0.f; a1[i] = 0.f; }
    #pragma unroll 1
    for (int d = 0; d < 210; d++) {
        float v0 = x2[d*L2D + base + tid];
        float v1 = x2[d*L2D + base + tid + 256];
        #pragma unroll
        for (int co = 0; co < 32; co++) {
            float w = s_w[co*210 + d];
            a0[co] += w*v0; a1[co] += w*v1;
        }
    }
    int lane = tid & 31, w = tid >> 5;
    #pragma unroll
    for (int co = 0; co < 32; co++) {
        float cc = g_c2[cb+co];
        float v0 = a0[co] + cc, v1 = a1[co] + cc;
        g_bufP[(cb+co)*L2D + base + tid]       = v0;
        g_bufP[(cb+co)*L2D + base + tid + 256] = v1;
        float s = v0 + v1, q = v0*v0 + v1*v1;
        #pragma unroll
        for (int o = 16; o; o >>= 1) {
            s += __shfl_down_sync(0xffffffffu, s, o);
            q += __shfl_down_sync(0xffffffffu, q, o);
        }
        if (lane == 0) { s_red[(w*32+co)*2] = s; s_red[(w*32+co)*2+1] = q; }
    }
    __syncthreads();
    if (tid < 32) {
        float s = 0.f, q = 0.f;
        for (int i = 0; i < 8; i++) { s += s_red[(i*32+tid)*2]; q += s_red[(i*32+tid)*2+1]; }
        atomicAdd(&g_statS[cb+tid], (double)s);
        atomicAdd(&g_statQ[cb+tid], (double)q);
    }
}

// ---------------- finalize stats ----------------
__global__ void k_fin(int idx, const float* __restrict__ g, const float* __restrict__ b) {
    int c = threadIdx.x;
    float mu = (float)(g_statS[idx*64+c] * NPIX_INV);
    float var = (float)(g_statQ[idx*64+c] * NPIX_INV) - mu*mu;
    float iv = rsqrtf(var + 1e-5f);
    g_nsc[idx*64+c] = g[c]*iv;
    g_nsh[idx*64+c] = b[c] - g[c]*iv*mu;
}

// ---------------- mix (stats idx 1) ----------------
__global__ void __launch_bounds__(256) k5_mix(const float* __restrict__ W3) {
    __shared__ float s_w3[64*128];
    __shared__ float s_red[8*64*2];
    __shared__ float s_a[64], s_b[64];
    int tid = threadIdx.x;
    for (int i = tid; i < 64*128; i += 256) s_w3[i] = W3[i];
    if (tid < 64) { s_a[tid] = g_nsc[tid]; s_b[tid] = g_nsh[tid]; }
    __syncthreads();
    int pix = blockIdx.x*256 + tid;
    int i = pix / 384, j = pix - i*384;
    float acc[64];
    #pragma unroll
    for (int c = 0; c < 64; c++) acc[c] = 0.f;
    #pragma unroll 1
    for (int c = 0; c < 64; c++) {
        float p2 = g_bufP[c*L2D + pix];
        p2 = lrelu(s_a[c]*p2 + s_b[c]);
        float p1 = lrelu(g_Ag[c*384+i] + g_Bg[c*384+j]);
        #pragma unroll
        for (int co = 0; co < 64; co++)
            acc[co] += s_w3[co*128 + c]*p1 + s_w3[co*128 + 64 + c]*p2;
    }
    int lane = tid & 31, w = tid >> 5;
    #pragma unroll
    for (int co = 0; co < 64; co++) {
        float v = acc[co];
        g_bufR[co*L2D + pix] = v;
        float s = v, q = v*v;
        #pragma unroll
        for (int o = 16; o; o >>= 1) {
            s += __shfl_down_sync(0xffffffffu, s, o);
            q += __shfl_down_sync(0xffffffffu, q, o);
        }
        if (lane == 0) { s_red[(w*64+co)*2] = s; s_red[(w*64+co)*2+1] = q; }
    }
    __syncthreads();
    if (tid < 64) {
        float s = 0.f, q = 0.f;
        for (int k = 0; k < 8; k++) { s += s_red[(k*64+tid)*2]; q += s_red[(k*64+tid)*2+1]; }
        atomicAdd(&g_statS[64+tid], (double)s);
        atomicAdd(&g_statQ[64+tid], (double)q);
    }
}

// ---------------- normalize + leaky (+ residual) ----------------
__global__ void k_apply(const float* __restrict__ raw, int idx,
                        const float* __restrict__ res, float* __restrict__ out) {
    int i = blockIdx.x*256 + threadIdx.x;
    int c = i / L2D;
    float v = raw[i]*g_nsc[idx*64+c] + g_nsh[idx*64+c];
    v = lrelu(v);
    if (res) v += res[i];
    out[i] = v;
}

// ---------------- per-channel stats over conv output ----------------
__global__ void k_stats(const float* __restrict__ buf, int idx) {
    __shared__ float sm[32];
    int c = blockIdx.y;
    const float* p = buf + c*L2D + blockIdx.x*2048;
    float s = 0.f, q = 0.f;
    #pragma unroll
    for (int k = 0; k < 8; k++) { float v = p[threadIdx.x + k*256]; s += v; q += v*v; }
    blockReduce2(s, q, sm);
    if (threadIdx.x == 0) {
        atomicAdd(&g_statS[idx*64+c], (double)s);
        atomicAdd(&g_statQ[idx*64+c], (double)q);
    }
}

// ================= mma.sync tf32 implicit-GEMM conv =================
// CTA: 128 px (one row segment) x 64 cout, K=576 in 18 chunks of 32.
// SMEM: sW [576][68] (pad 4), sA [2][128][36] (pad 4).
#define SW_STRIDE 68
#define SA_STRIDE 36
#define CONV_SMEM ((576*SW_STRIDE + 2*128*SA_STRIDE)*4)

__global__ void __launch_bounds__(256, 1)
conv_mma(const float* __restrict__ in, int l2k, int D,
         const float* __restrict__ bias, float* __restrict__ out)
{
    extern __shared__ float smf[];
    float* sW = smf;                      // 576*68
    float* sA = smf + 576*SW_STRIDE;      // 2 * 128*36
    __shared__ float s_bias[64];

    int tid = threadIdx.x, lane = tid & 31, wid = tid >> 5;
    int x0 = blockIdx.x * 128, y = blockIdx.y;
    int wm = wid & 3, wn = wid >> 2;      // 4 px-groups x 2 co-groups

    if (tid < 64) s_bias[tid] = bias[tid];

    const float* wsrc = g_wsw + l2k*36864;
    for (int i = tid; i < 36864; i += 256)
        sW[(i >> 6)*SW_STRIDE + (i & 63)] = wsrc[i];

    float acc[2][4][4];
    #pragma unroll
    for (int mt = 0; mt < 2; mt++)
        #pragma unroll
        for (int nt = 0; nt < 4; nt++)
            #pragma unroll
            for (int r = 0; r < 4; r++) acc[mt][nt][r] = 0.f;

    float4 stg[4];

    // gather chunk c = (tap, half) into registers (coalesced along px)
    auto ldchunk = [&](int c) {
        int tap = c >> 1, h = c & 1;
        int dy = (tap/3 - 1)*D, dx = (tap%3 - 1)*D;
        int gy = y + dy;
        bool gyok = ((unsigned)gy < 384u);
        const float* ip = in + gy*IMG;
        #pragma unroll
        for (int r = 0; r < 4; r++) {
            int e = tid + r*256;
            int px = e & 127, cq = e >> 7;   // cq = k-quad 0..7
            int gx = x0 + px + dx;
            float4 v = make_float4(0.f, 0.f, 0.f, 0.f);
            if (gyok && (unsigned)gx < 384u) {
                const float* p = ip + (h*32 + cq*4)*L2D + gx;
                v.x = __uint_as_float(cvt_tf32(p[0]));
                v.y = __uint_as_float(cvt_tf32(p[L2D]));
                v.z = __uint_as_float(cvt_tf32(p[2*L2D]));
                v.w = __uint_as_float(cvt_tf32(p[3*L2D]));
            }
            stg[r] = v;
        }
    };
    auto stchunk = [&](int b) {
        float* abuf = sA + b*128*SA_STRIDE;
        #pragma unroll
        for (int r = 0; r < 4; r++) {
            int e = tid + r*256;
            int px = e & 127, cq = e >> 7;
            *(float4*)&abuf[px*SA_STRIDE + cq*4] = stg[r];
        }
    };

    ldchunk(0);
    stchunk(0);
    __syncthreads();

    int rA = lane >> 2, qA = lane & 3;
    #pragma unroll 1
    for (int c = 0; c < 18; c++) {
        int b = c & 1;
        if (c + 1 < 18) ldchunk(c + 1);          // global loads in flight

        const uint32_t* Abase = (const uint32_t*)(sA + b*128*SA_STRIDE) + wm*32*SA_STRIDE;
        const uint32_t* Bbase = (const uint32_t*)sW + wn*32;
        #pragma unroll
        for (int ks = 0; ks < 4; ks++) {
            int kg = c*32 + ks*8;
            uint32_t a[2][4];
            #pragma unroll
            for (int mt = 0; mt < 2; mt++) {
                const uint32_t* Ap = Abase + mt*16*SA_STRIDE + ks*8;
                a[mt][0] = Ap[rA*SA_STRIDE + qA];
                a[mt][1] = Ap[(rA+8)*SA_STRIDE + qA];
                a[mt][2] = Ap[rA*SA_STRIDE + qA + 4];
                a[mt][3] = Ap[(rA+8)*SA_STRIDE + qA + 4];
            }
            uint32_t bf[4][2];
            #pragma unroll
            for (int nt = 0; nt < 4; nt++) {
                const uint32_t* Bp = Bbase + kg*SW_STRIDE + nt*8 + rA;
                bf[nt][0] = Bp[qA*SW_STRIDE];
                bf[nt][1] = Bp[(qA+4)*SW_STRIDE];
            }
            #pragma unroll
            for (int mt = 0; mt < 2; mt++)
                #pragma unroll
                for (int nt = 0; nt < 4; nt++)
                    mma_tf32_16n8k8(acc[mt][nt], a[mt], bf[nt]);
        }
        __syncthreads();                          // all warps done reading buffer b
        if (c + 1 < 18) {
            stchunk(b ^ 1);                       // b^1 was consumed in iter c-1
            __syncthreads();
        }
    }

    // epilogue: C frag (m16n8): c0/c1 row=lane/4 cols 2q,2q+1; c2/c3 row+8
    int gbase = y*IMG + x0 + wm*32;
    #pragma unroll
    for (int mt = 0; mt < 2; mt++) {
        int px = gbase + mt*16 + rA;
        #pragma unroll
        for (int nt = 0; nt < 4; nt++) {
            int co0 = wn*32 + nt*8 + 2*qA;
            out[co0*L2D + px]           = acc[mt][nt][0] + s_bias[co0];
            out[(co0+1)*L2D + px]       = acc[mt][nt][1] + s_bias[co0+1];
            out[co0*L2D + px + 8]       = acc[mt][nt][2] + s_bias[co0];
            out[(co0+1)*L2D + px + 8]   = acc[mt][nt][3] + s_bias[co0+1];
        }
    }
}

// ---------------- launch ----------------
extern "C" void kernel_launch(void* const* d_in, const int* in_sizes, int n_in,
                              void* d_out, int out_size) {
    const float* x1d  = (const float*)d_in[0];
    const float* x2   = (const float*)d_in[1];
    const float* W1   = (const float*)d_in[2];
    const float* g1   = (const float*)d_in[3];
    const float* b1   = (const float*)d_in[4];
    const float* W2   = (const float*)d_in[5];
    const float* g2   = (const float*)d_in[6];
    const float* b2   = (const float*)d_in[7];
    const float* W3   = (const float*)d_in[8];
    const float* g3   = (const float*)d_in[9];
    const float* b3   = (const float*)d_in[10];
    const float* rw   = (const float*)d_in[11];
    const float* rb   = (const float*)d_in[12];
    const float* rg   = (const float*)d_in[13];
    const float* rbe  = (const float*)d_in[14];
    float* out = (float*)d_out;

    float *bP, *bR, *bX, *bT;
    cudaGetSymbolAddress((void**)&bP, g_bufP);
    cudaGetSymbolAddress((void**)&bR, g_bufR);
    cudaGetSymbolAddress((void**)&bX, g_bufX);
    cudaGetSymbolAddress((void**)&bT, g_bufT);

    cudaFuncSetAttribute(conv_mma, cudaFuncAttributeMaxDynamicSharedMemorySize, CONV_SMEM);

    k_zero<<<4, 256>>>();
    k_wprep<<<1440, 256>>>(rw);
    k1_norm1d<<<788, 384>>>(x1d);
    k2_x2stats<<<dim3(36, 210), 256>>>(x2);
    k2b_scaleW2<<<1, 256>>>(W2);
    k3_rowcol<<<128, 384>>>(W1);
    k3b_pair1<<<64, 128>>>(g1, b1);
    k4_pair2<<<dim3(288, 2), 256>>>(x2);
    k_fin<<<1, 64>>>(0, g2, b2);
    k5_mix<<<576, 256>>>(W3);
    k_fin<<<1, 64>>>(1, g3, b3);
    k_apply<<<36864, 256>>>(bR, 1, nullptr, bX);

    float* cur = bX;
    float* other = bP;
    const int DIL[5] = {1, 2, 4, 2, 1};
    for (int l = 0; l < 5; l++) {
        for (int k = 0; k < 2; k++) {
            int si = 2 + l*2 + k;
            int l2k = l*2 + k;
            const float* bk  = rb  + l2k*64;
            const float* gk  = rg  + l2k*64;
            const float* bbk = rbe + l2k*64;
            const float* src = (k == 0) ? cur : bT;
            conv_mma<<<dim3(3, 384), 256, CONV_SMEM>>>(src, l2k, DIL[l], bk, bR);
            k_stats<<<dim3(72, 64), 256>>>(bR, si);
            k_fin<<<1, 64>>>(si, gk, bbk);
            if (k == 0) {
                k_apply<<<36864, 256>>>(bR, si, nullptr, bT);
            } else {
                float* dst = (l == 4) ? out : other;
                k_apply<<<36864, 256>>>(bR, si, cur, dst);
                if (l < 4) { float* tmp = cur; cur = other; other = tmp; }
            }
        }
    }
}

// round 8
// speedup vs baseline: 2.5394x; 1.7238x over previous
#include <cuda_runtime.h>
#include <cuda_bf16.h>
#include <cstdint>

#define L2D 147456   // 384*384
#define IMG 384
#define NPIX_INV (1.0/147456.0)

// ---------------- static scratch ----------------
__device__ float g_x1n[788*384];
__device__ float g_row[64*384];
__device__ float g_col[64*384];
__device__ float g_Ag[64*384];
__device__ float g_Bg[64*384];
__device__ float g_W2s[64*210];
__device__ float g_c2[64];
__device__ double g_x2s[210];
__device__ double g_x2q[210];
__device__ double g_statS[16*64];
__device__ double g_statQ[16*64];
__device__ float g_nsc[16*64];
__device__ float g_nsh[16*64];

__device__ float g_wsw[10*576*64];   // tf32-rounded weights, [l2k][k=tap*64+ci][co]
__device__ float g_pS[64*1152];      // per-CTA partial sums (deterministic)
__device__ float g_pQ[64*1152];

__device__ float g_bufP[64*L2D];
__device__ float g_bufR[64*L2D];
__device__ float g_bufX[64*L2D];
__device__ float g_bufT[64*L2D];

// ---------------- helpers ----------------
__device__ __forceinline__ uint32_t cvt_tf32(float v){
    uint32_t u; asm("cvt.rna.tf32.f32 %0, %1;" : "=r"(u) : "f"(v)); return u;
}

__device__ __forceinline__ void mma_tf32_16n8k8(float* c, const uint32_t* a, const uint32_t* b){
    asm volatile("mma.sync.aligned.m16n8k8.row.col.f32.tf32.tf32.f32 "
        "{%0,%1,%2,%3}, {%4,%5,%6,%7}, {%8,%9}, {%0,%1,%2,%3};"
        : "+f"(c[0]), "+f"(c[1]), "+f"(c[2]), "+f"(c[3])
        : "r"(a[0]), "r"(a[1]), "r"(a[2]), "r"(a[3]), "r"(b[0]), "r"(b[1]));
}

__device__ __forceinline__ void blockReduce2(float& s, float& q, float* sm) {
    __syncthreads();
    int lane = threadIdx.x & 31, w = threadIdx.x >> 5;
    #pragma unroll
    for (int o = 16; o; o >>= 1) {
        s += __shfl_down_sync(0xffffffffu, s, o);
        q += __shfl_down_sync(0xffffffffu, q, o);
    }
    if (lane == 0) { sm[2*w] = s; sm[2*w+1] = q; }
    __syncthreads();
    int nw = blockDim.x >> 5;
    if (threadIdx.x == 0) {
        float S = 0.f, Q = 0.f;
        for (int i = 0; i < nw; i++) { S += sm[2*i]; Q += sm[2*i+1]; }
        sm[0] = S; sm[1] = Q;
    }
    __syncthreads();
    s = sm[0]; q = sm[1];
}

__device__ __forceinline__ float lrelu(float v) { return v < 0.f ? 0.01f*v : v; }

// ---------------- zero stats ----------------
__global__ void k_zero() {
    int t = blockIdx.x*256 + threadIdx.x;
    if (t < 16*64) { g_statS[t] = 0.0; g_statQ[t] = 0.0; }
    if (t < 210)   { g_x2s[t] = 0.0;  g_x2q[t] = 0.0; }
}

// ---------------- weight prep: tf32 round, reorder to [l2k][k][co] ----------------
__global__ void k_wprep(const float* __restrict__ rw) {
    int i = blockIdx.x*256 + threadIdx.x;
    if (i >= 10*64*64*9) return;
    int tap = i % 9; int r = i / 9;
    int ci = r & 63; r >>= 6;
    int co = r & 63; int l2k = r >> 6;
    g_wsw[l2k*36864 + (tap*64 + ci)*64 + co] = __uint_as_float(cvt_tf32(rw[i]));
}

// ---------------- x_1d instance norm ----------------
__global__ void k1_norm1d(const float* __restrict__ x) {
    __shared__ float sm[32];
    int d = blockIdx.x;
    float v = x[d*384 + threadIdx.x];
    float s = v, q = v*v;
    blockReduce2(s, q, sm);
    float mu = s * (1.f/384.f);
    float var = q * (1.f/384.f) - mu*mu;
    float iv = rsqrtf(var + 1e-5f);
    g_x1n[d*384 + threadIdx.x] = (v - mu) * iv;
}

// ---------------- x_2d per-channel stats (float4) ----------------
__global__ void k2_x2stats(const float* __restrict__ x2) {
    __shared__ float sm[32];
    int c = blockIdx.y;
    const float4* p = (const float4*)(x2 + c*L2D + blockIdx.x*4096);
    float s = 0.f, q = 0.f;
    #pragma unroll
    for (int k = 0; k < 4; k++) {
        float4 v = p[threadIdx.x + k*256];
        s += v.x + v.y + v.z + v.w;
        q += v.x*v.x + v.y*v.y + v.z*v.z + v.w*v.w;
    }
    blockReduce2(s, q, sm);
    if (threadIdx.x == 0) {
        atomicAdd(&g_x2s[c], (double)s);
        atomicAdd(&g_x2q[c], (double)q);
    }
}

// ---------------- fold x2 norm into W2 ----------------
__global__ void k2b_scaleW2(const float* __restrict__ W2) {
    __shared__ float smu[210], siv[210];
    int t = threadIdx.x;
    if (t < 210) {
        float mu = (float)(g_x2s[t] * NPIX_INV);
        float var = (float)(g_x2q[t] * NPIX_INV) - mu*mu;
        smu[t] = mu; siv[t] = rsqrtf(var + 1e-5f);
    }
    __syncthreads();
    for (int i = t; i < 64*210; i += blockDim.x) g_W2s[i] = W2[i] * siv[i % 210];
    if (t < 64) {
        float a = 0.f;
        for (int d = 0; d < 210; d++) a += W2[t*210+d] * smu[d] * siv[d];
        g_c2[t] = -a;
    }
}

// ---------------- row/col projections ----------------
__global__ void k3_rowcol(const float* __restrict__ W1) {
    int c = blockIdx.x >> 1, which = blockIdx.x & 1;
    const float* w = W1 + c*1576 + which*788;
    int l = threadIdx.x;
    float acc = 0.f;
    #pragma unroll 4
    for (int d = 0; d < 788; d++) acc += w[d] * g_x1n[d*384 + l];
    (which ? g_col : g_row)[c*384 + l] = acc;
}

// ---------------- pair1 separable stats ----------------
__global__ void k3b_pair1(const float* __restrict__ g1, const float* __restrict__ b1) {
    __shared__ float sm[32];
    int c = blockIdx.x, t = threadIdx.x;
    float sr = 0.f, qr = 0.f, sc_ = 0.f, qc = 0.f;
    for (int i = t; i < 384; i += 128) {
        float r = g_row[c*384+i]; sr += r; qr += r*r;
        float cl = g_col[c*384+i]; sc_ += cl; qc += cl*cl;
    }
    blockReduce2(sr, qr, sm);
    blockReduce2(sc_, qc, sm);
    float mur = sr*(1.f/384.f), muc = sc_*(1.f/384.f);
    float var = (qr*(1.f/384.f) - mur*mur) + (qc*(1.f/384.f) - muc*muc);
    float iv = rsqrtf(var + 1e-5f);
    float mu = mur + muc;
    float gc = g1[c], bc = b1[c];
    for (int i = t; i < 384; i += 128) {
        g_Ag[c*384+i] = gc*iv*(g_row[c*384+i] - mu) + bc;
        g_Bg[c*384+i] = gc*iv*g_col[c*384+i];
    }
}

// ---------------- pair2 = W2s @ x2 + c2 (stats idx 0) ----------------
__global__ void __launch_bounds__(256) k4_pair2(const float* __restrict__ x2) {
    __shared__ float s_w[32*210];
    __shared__ float s_red[8*32*2];
    int tid = threadIdx.x;
    int base = blockIdx.x * 512;
    int cb = blockIdx.y * 32;
    for (int i = tid; i < 32*210; i += 256) s_w[i] = g_W2s[cb*210 + i];
    __syncthreads();
    float a0[32], a1[32];
    #pragma unroll
    for (int i = 0; i < 32; i++) { a0[i] = 0.f; a1[i] = 0.f; }
    #pragma unroll 1
    for (int d = 0; d < 210; d++) {
        float v0 = x2[d*L2D + base + tid];
        float v1 = x2[d*L2D + base + tid + 256];
        #pragma unroll
        for (int co = 0; co < 32; co++) {
            float w = s_w[co*210 + d];
            a0[co] += w*v0; a1[co] += w*v1;
        }
    }
    int lane = tid & 31, w = tid >> 5;
    #pragma unroll
    for (int co = 0; co < 32; co++) {
        float cc = g_c2[cb+co];
        float v0 = a0[co] + cc, v1 = a1[co] + cc;
        g_bufP[(cb+co)*L2D + base + tid]       = v0;
        g_bufP[(cb+co)*L2D + base + tid + 256] = v1;
        float s = v0 + v1, q = v0*v0 + v1*v1;
        #pragma unroll
        for (int o = 16; o; o >>= 1) {
            s += __shfl_down_sync(0xffffffffu, s, o);
            q += __shfl_down_sync(0xffffffffu, q, o);
        }
        if (lane == 0) { s_red[(w*32+co)*2] = s; s_red[(w*32+co)*2+1] = q; }
    }
    __syncthreads();
    if (tid < 32) {
        float s = 0.f, q = 0.f;
        for (int i = 0; i < 8; i++) { s += s_red[(i*32+tid)*2]; q += s_red[(i*32+tid)*2+1]; }
        atomicAdd(&g_statS[cb+tid], (double)s);
        atomicAdd(&g_statQ[cb+tid], (double)q);
    }
}

// ---------------- finalize stats (atomic path, idx 0/1) ----------------
__global__ void k_fin(int idx, const float* __restrict__ g, const float* __restrict__ b) {
    int c = threadIdx.x;
    float mu = (float)(g_statS[idx*64+c] * NPIX_INV);
    float var = (float)(g_statQ[idx*64+c] * NPIX_INV) - mu*mu;
    float iv = rsqrtf(var + 1e-5f);
    g_nsc[idx*64+c] = g[c]*iv;
    g_nsh[idx*64+c] = b[c] - g[c]*iv*mu;
}

// ---------------- finalize stats from conv partials ----------------
__global__ void k_finred(int idx, const float* __restrict__ g, const float* __restrict__ b) {
    __shared__ float sm[32];
    int ch = blockIdx.x;
    float s = 0.f, q = 0.f;
    for (int i = threadIdx.x; i < 1152; i += 256) {
        s += g_pS[ch*1152 + i];
        q += g_pQ[ch*1152 + i];
    }
    blockReduce2(s, q, sm);
    if (threadIdx.x == 0) {
        float mu = s * (float)NPIX_INV;
        float var = q * (float)NPIX_INV - mu*mu;
        float iv = rsqrtf(var + 1e-5f);
        g_nsc[idx*64+ch] = g[ch]*iv;
        g_nsh[idx*64+ch] = b[ch] - g[ch]*iv*mu;
    }
}

// ---------------- mix (stats idx 1) ----------------
__global__ void __launch_bounds__(256) k5_mix(const float* __restrict__ W3) {
    __shared__ float s_w3[64*128];
    __shared__ float s_red[8*64*2];
    __shared__ float s_a[64], s_b[64];
    int tid = threadIdx.x;
    for (int i = tid; i < 64*128; i += 256) s_w3[i] = W3[i];
    if (tid < 64) { s_a[tid] = g_nsc[tid]; s_b[tid] = g_nsh[tid]; }
    __syncthreads();
    int pix = blockIdx.x*256 + tid;
    int i = pix / 384, j = pix - i*384;
    float acc[64];
    #pragma unroll
    for (int c = 0; c < 64; c++) acc[c] = 0.f;
    #pragma unroll 1
    for (int c = 0; c < 64; c++) {
        float p2 = g_bufP[c*L2D + pix];
        p2 = lrelu(s_a[c]*p2 + s_b[c]);
        float p1 = lrelu(g_Ag[c*384+i] + g_Bg[c*384+j]);
        #pragma unroll
        for (int co = 0; co < 64; co++)
            acc[co] += s_w3[co*128 + c]*p1 + s_w3[co*128 + 64 + c]*p2;
    }
    int lane = tid & 31, w = tid >> 5;
    #pragma unroll
    for (int co = 0; co < 64; co++) {
        float v = acc[co];
        g_bufR[co*L2D + pix] = v;
        float s = v, q = v*v;
        #pragma unroll
        for (int o = 16; o; o >>= 1) {
            s += __shfl_down_sync(0xffffffffu, s, o);
            q += __shfl_down_sync(0xffffffffu, q, o);
        }
        if (lane == 0) { s_red[(w*64+co)*2] = s; s_red[(w*64+co)*2+1] = q; }
    }
    __syncthreads();
    if (tid < 64) {
        float s = 0.f, q = 0.f;
        for (int k = 0; k < 8; k++) { s += s_red[(k*64+tid)*2]; q += s_red[(k*64+tid)*2+1]; }
        atomicAdd(&g_statS[64+tid], (double)s);
        atomicAdd(&g_statQ[64+tid], (double)q);
    }
}

// ---------------- normalize + leaky (+ residual), float4 ----------------
__global__ void k_apply4(const float4* __restrict__ raw, int idx,
                         const float4* __restrict__ res, float4* __restrict__ out) {
    int i = blockIdx.x*256 + threadIdx.x;          // 64*L2D/4 = 2359296 elems
    int c = i / (L2D/4);
    float sc = g_nsc[idx*64+c], sh = g_nsh[idx*64+c];
    float4 v = raw[i];
    v.x = lrelu(v.x*sc + sh);
    v.y = lrelu(v.y*sc + sh);
    v.z = lrelu(v.z*sc + sh);
    v.w = lrelu(v.w*sc + sh);
    if (res) {
        float4 r = res[i];
        v.x += r.x; v.y += r.y; v.z += r.z; v.w += r.w;
    }
    out[i] = v;
}

// ================= mma.sync tf32 implicit-GEMM conv =================
// CTA: 128 px x 64 cout, K=576 in 18 chunks of 32 (tap x ci-half).
// Weights streamed per-chunk (8KB) -> smem 55KB -> 2 CTAs/SM. One sync/chunk.
// Epilogue: bias + raw store + per-CTA channel partial stats (deterministic).
#define SW_STRIDE 72   // 8*qA+rA bank pattern: conflict-free B-frag loads
#define SA_STRIDE 36
#define CONV_SMEM ((2*128*SA_STRIDE + 2*32*SW_STRIDE)*4)

template<bool APPLY>
__global__ void __launch_bounds__(256, 2)
conv_mma(const float* __restrict__ in, int aidx, const float* __restrict__ wsrc,
         int D, const float* __restrict__ bias, float* __restrict__ out)
{
    extern __shared__ float smf[];
    float* sA = smf;                        // 2 * 128*36
    float* sW = smf + 2*128*SA_STRIDE;      // 2 * 32*72
    __shared__ float s_bias[64];
    __shared__ float s_nsc[64], s_nsh[64];
    __shared__ float s_rs[8][4][8], s_rq[8][4][8];

    int tid = threadIdx.x, lane = tid & 31, wid = tid >> 5;
    int x0 = blockIdx.x * 128, y = blockIdx.y;
    int cta = blockIdx.y * 3 + blockIdx.x;
    int wm = wid & 3, wn = wid >> 2;
    int rA = lane >> 2, qA = lane & 3;

    if (tid < 64) {
        s_bias[tid] = bias[tid];
        if (APPLY) { s_nsc[tid] = g_nsc[aidx*64 + tid]; s_nsh[tid] = g_nsh[aidx*64 + tid]; }
    }
    if (APPLY) __syncthreads();   // gather needs s_nsc/s_nsh

    float acc[2][4][4];
    #pragma unroll
    for (int mt = 0; mt < 2; mt++)
        #pragma unroll
        for (int nt = 0; nt < 4; nt++)
            #pragma unroll
            for (int r = 0; r < 4; r++) acc[mt][nt][r] = 0.f;

    float4 stg[4];
    float4 wstg[2];

    auto ldchunk = [&](int c) {
        int tap = c >> 1, h = c & 1;
        int dy = (tap/3 - 1)*D, dx = (tap%3 - 1)*D;
        int gy = y + dy;
        bool gyok = ((unsigned)gy < 384u);
        const float* ip = in + gy*IMG;
        #pragma unroll
        for (int r = 0; r < 4; r++) {
            int e = tid + r*256;
            int px = e & 127, cq = e >> 7;
            int gx = x0 + px + dx;
            float4 v = make_float4(0.f, 0.f, 0.f, 0.f);
            if (gyok && (unsigned)gx < 384u) {
                int cb = h*32 + cq*4;
                const float* p = ip + cb*L2D + gx;
                float f0 = p[0], f1 = p[L2D], f2 = p[2*L2D], f3 = p[3*L2D];
                if (APPLY) {
                    f0 = lrelu(f0*s_nsc[cb]   + s_nsh[cb]);
                    f1 = lrelu(f1*s_nsc[cb+1] + s_nsh[cb+1]);
                    f2 = lrelu(f2*s_nsc[cb+2] + s_nsh[cb+2]);
                    f3 = lrelu(f3*s_nsc[cb+3] + s_nsh[cb+3]);
                }
                v.x = __uint_as_float(cvt_tf32(f0));
                v.y = __uint_as_float(cvt_tf32(f1));
                v.z = __uint_as_float(cvt_tf32(f2));
                v.w = __uint_as_float(cvt_tf32(f3));
            }
            stg[r] = v;
        }
    };
    auto stchunk = [&](int b) {
        float* abuf = sA + b*128*SA_STRIDE;
        #pragma unroll
        for (int r = 0; r < 4; r++) {
            int e = tid + r*256;
            int px = e & 127, cq = e >> 7;
            *(float4*)&abuf[px*SA_STRIDE + cq*4] = stg[r];
        }
    };
    auto ldw = [&](int c) {
        const float4* p = (const float4*)(wsrc + c*2048);
        wstg[0] = p[tid];
        wstg[1] = p[tid + 256];
    };
    auto stw = [&](int b) {
        float* wb = sW + b*32*SW_STRIDE;
        int k0 = tid >> 4, co0 = (tid & 15) * 4;
        *(float4*)&wb[k0*SW_STRIDE + co0]        = wstg[0];
        *(float4*)&wb[(k0+16)*SW_STRIDE + co0]   = wstg[1];
    };

    ldchunk(0); ldw(0);
    stchunk(0); stw(0);
    __syncthreads();

    #pragma unroll 1
    for (int c = 0; c < 18; c++) {
        int b = c & 1;
        if (c + 1 < 18) { ldchunk(c + 1); ldw(c + 1); }   // global loads in flight

        const uint32_t* Abase = (const uint32_t*)(sA + b*128*SA_STRIDE) + wm*32*SA_STRIDE;
        const uint32_t* Bbase = (const uint32_t*)(sW + b*32*SW_STRIDE) + wn*32;
        #pragma unroll
        for (int ks = 0; ks < 4; ks++) {
            uint32_t a[2][4];
            #pragma unroll
            for (int mt = 0; mt < 2; mt++) {
                const uint32_t* Ap = Abase + mt*16*SA_STRIDE + ks*8;
                a[mt][0] = Ap[rA*SA_STRIDE + qA];
                a[mt][1] = Ap[(rA+8)*SA_STRIDE + qA];
                a[mt][2] = Ap[rA*SA_STRIDE + qA + 4];
                a[mt][3] = Ap[(rA+8)*SA_STRIDE + qA + 4];
            }
            uint32_t bf[4][2];
            #pragma unroll
            for (int nt = 0; nt < 4; nt++) {
                const uint32_t* Bp = Bbase + ks*8*SW_STRIDE + nt*8 + rA;
                bf[nt][0] = Bp[qA*SW_STRIDE];
                bf[nt][1] = Bp[(qA+4)*SW_STRIDE];
            }
            #pragma unroll
            for (int mt = 0; mt < 2; mt++)
                #pragma unroll
                for (int nt = 0; nt < 4; nt++)
                    mma_tf32_16n8k8(acc[mt][nt], a[mt], bf[nt]);
        }
        // store next chunk into the other buffer: its readers finished before the
        // sync at the end of the previous iteration -> single sync per chunk.
        if (c + 1 < 18) { stchunk(b ^ 1); stw(b ^ 1); }
        __syncthreads();
    }

    // ---- epilogue: bias + store raw + per-channel partial stats ----
    float ss[4][2], qq[4][2];
    #pragma unroll
    for (int nt = 0; nt < 4; nt++) { ss[nt][0]=0.f; ss[nt][1]=0.f; qq[nt][0]=0.f; qq[nt][1]=0.f; }
    int gbase = y*IMG + x0 + wm*32;
    #pragma unroll
    for (int nt = 0; nt < 4; nt++) {
        int coA = wn*32 + nt*8 + 2*qA;
        float bA = s_bias[coA], bB = s_bias[coA+1];
        #pragma unroll
        for (int mt = 0; mt < 2; mt++) {
            int px = gbase + mt*16 + rA;
            float v0 = acc[mt][nt][0] + bA;
            float v1 = acc[mt][nt][1] + bB;
            float v2 = acc[mt][nt][2] + bA;
            float v3 = acc[mt][nt][3] + bB;
            out[coA*L2D + px]         = v0;
            out[(coA+1)*L2D + px]     = v1;
            out[coA*L2D + px + 8]     = v2;
            out[(coA+1)*L2D + px + 8] = v3;
            ss[nt][0] += v0 + v2;  qq[nt][0] += v0*v0 + v2*v2;
            ss[nt][1] += v1 + v3;  qq[nt][1] += v1*v1 + v3*v3;
        }
    }
    #pragma unroll
    for (int nt = 0; nt < 4; nt++)
        #pragma unroll
        for (int e = 0; e < 2; e++) {
            float s = ss[nt][e], q = qq[nt][e];
            s += __shfl_down_sync(0xffffffffu, s, 16);
            q += __shfl_down_sync(0xffffffffu, q, 16);
            s += __shfl_down_sync(0xffffffffu, s, 8);
            q += __shfl_down_sync(0xffffffffu, q, 8);
            s += __shfl_down_sync(0xffffffffu, s, 4);
            q += __shfl_down_sync(0xffffffffu, q, 4);
            ss[nt][e] = s; qq[nt][e] = q;
        }
    if (lane < 4) {
        #pragma unroll
        for (int nt = 0; nt < 4; nt++) {
            s_rs[wid][lane][nt*2]   = ss[nt][0];  s_rq[wid][lane][nt*2]   = qq[nt][0];
            s_rs[wid][lane][nt*2+1] = ss[nt][1];  s_rq[wid][lane][nt*2+1] = qq[nt][1];
        }
    }
    __syncthreads();
    if (tid < 64) {
        int wn2 = tid >> 5, rem = tid & 31;
        int nt = rem >> 3, low = rem & 7, qa2 = low >> 1, e = low & 1;
        float s = 0.f, q = 0.f;
        #pragma unroll
        for (int wm2 = 0; wm2 < 4; wm2++) {
            s += s_rs[wn2*4 + wm2][qa2][nt*2 + e];
            q += s_rq[wn2*4 + wm2][qa2][nt*2 + e];
        }
        g_pS[tid*1152 + cta] = s;
        g_pQ[tid*1152 + cta] = q;
    }
}

// ---------------- launch ----------------
extern "C" void kernel_launch(void* const* d_in, const int* in_sizes, int n_in,
                              void* d_out, int out_size) {
    const float* x1d  = (const float*)d_in[0];
    const float* x2   = (const float*)d_in[1];
    const float* W1   = (const float*)d_in[2];
    const float* g1   = (const float*)d_in[3];
    const float* b1   = (const float*)d_in[4];
    const float* W2   = (const float*)d_in[5];
    const float* g2   = (const float*)d_in[6];
    const float* b2   = (const float*)d_in[7];
    const float* W3   = (const float*)d_in[8];
    const float* g3   = (const float*)d_in[9];
    const float* b3   = (const float*)d_in[10];
    const float* rw   = (const float*)d_in[11];
    const float* rb   = (const float*)d_in[12];
    const float* rg   = (const float*)d_in[13];
    const float* rbe  = (const float*)d_in[14];
    float* out = (float*)d_out;

    float *bP, *bR, *bX, *bT, *wswp;
    cudaGetSymbolAddress((void**)&bP, g_bufP);
    cudaGetSymbolAddress((void**)&bR, g_bufR);
    cudaGetSymbolAddress((void**)&bX, g_bufX);
    cudaGetSymbolAddress((void**)&bT, g_bufT);
    cudaGetSymbolAddress((void**)&wswp, g_wsw);

    cudaFuncSetAttribute(conv_mma<false>, cudaFuncAttributeMaxDynamicSharedMemorySize, CONV_SMEM);
    cudaFuncSetAttribute(conv_mma<true>,  cudaFuncAttributeMaxDynamicSharedMemorySize, CONV_SMEM);

    k_zero<<<4, 256>>>();
    k_wprep<<<1440, 256>>>(rw);
    k1_norm1d<<<788, 384>>>(x1d);
    k2_x2stats<<<dim3(36, 210), 256>>>(x2);
    k2b_scaleW2<<<1, 256>>>(W2);
    k3_rowcol<<<128, 384>>>(W1);
    k3b_pair1<<<64, 128>>>(g1, b1);
    k4_pair2<<<dim3(288, 2), 256>>>(x2);
    k_fin<<<1, 64>>>(0, g2, b2);
    k5_mix<<<576, 256>>>(W3);
    k_fin<<<1, 64>>>(1, g3, b3);
    k_apply4<<<9216, 256>>>((const float4*)bR, 1, nullptr, (float4*)bX);

    float* cur = bX;
    float* other = bP;
    const int DIL[5] = {1, 2, 4, 2, 1};
    dim3 cgrid(3, 384);
    for (int l = 0; l < 5; l++) {
        int D = DIL[l];
        int si0 = 2 + l*2, si1 = si0 + 1;
        // conv1: reads applied tensor, raw -> bR
        conv_mma<false><<<cgrid, 256, CONV_SMEM>>>(cur, 0, wswp + (l*2)*36864, D,
                                                   rb + (l*2)*64, bR);
        k_finred<<<64, 256>>>(si0, rg + (l*2)*64, rbe + (l*2)*64);
        // conv2: reads raw bR with inline norm+lrelu(si0), raw -> bT
        conv_mma<true><<<cgrid, 256, CONV_SMEM>>>(bR, si0, wswp + (l*2+1)*36864, D,
                                                  rb + (l*2+1)*64, bT);
        k_finred<<<64, 256>>>(si1, rg + (l*2+1)*64, rbe + (l*2+1)*64);
        // apply(si1) + residual
        float* dst = (l == 4) ? out : other;
        k_apply4<<<9216, 256>>>((const float4*)bT, si1, (const float4*)cur, (float4*)dst);
        if (l < 4) { float* tmp = cur; cur = other; other = tmp; }
    }
}

// round 10
// speedup vs baseline: 3.2600x; 1.2838x over previous
#include <cuda_runtime.h>
#include <cuda_fp16.h>
#include <cstdint>

#define L2D 147456   // 384*384
#define IMG 384
#define NPIX_INV (1.0/147456.0)

// ---------------- static scratch ----------------
__device__ float g_x1n[788*384];
__device__ float g_row[64*384];
__device__ float g_col[64*384];
__device__ float g_Ag[64*384];
__device__ float g_Bg[64*384];
__device__ float g_W2s[64*210];
__device__ float g_c2[64];
__device__ double g_x2s[210];
__device__ double g_x2q[210];
__device__ double g_statS[16*64];
__device__ double g_statQ[16*64];
__device__ float g_nsc[16*64];
__device__ float g_nsh[16*64];

__device__ __half g_wswh[10*64*576];   // fp16 weights, [l2k][co][k = tap*64 + ci]
__device__ float g_pS[64*1152];        // per-CTA partial sums (deterministic)
__device__ float g_pQ[64*1152];

__device__ float g_bufP[64*L2D];
__device__ float g_bufR[64*L2D];
__device__ float g_bufX[64*L2D];
__device__ float g_bufT[64*L2D];

// ---------------- helpers ----------------
__device__ __forceinline__ void mma_f16_16n8k16(float* c, const uint32_t* a, const uint32_t* b){
    asm volatile("mma.sync.aligned.m16n8k16.row.col.f32.f16.f16.f32 "
        "{%0,%1,%2,%3}, {%4,%5,%6,%7}, {%8,%9}, {%0,%1,%2,%3};"
        : "+f"(c[0]), "+f"(c[1]), "+f"(c[2]), "+f"(c[3])
        : "r"(a[0]), "r"(a[1]), "r"(a[2]), "r"(a[3]), "r"(b[0]), "r"(b[1]));
}

__device__ __forceinline__ void blockReduce2(float& s, float& q, float* sm) {
    __syncthreads();
    int lane = threadIdx.x & 31, w = threadIdx.x >> 5;
    #pragma unroll
    for (int o = 16; o; o >>= 1) {
        s += __shfl_down_sync(0xffffffffu, s, o);
        q += __shfl_down_sync(0xffffffffu, q, o);
    }
    if (lane == 0) { sm[2*w] = s; sm[2*w+1] = q; }
    __syncthreads();
    int nw = blockDim.x >> 5;
    if (threadIdx.x == 0) {
        float S = 0.f, Q = 0.f;
        for (int i = 0; i < nw; i++) { S += sm[2*i]; Q += sm[2*i+1]; }
        sm[0] = S; sm[1] = Q;
    }
    __syncthreads();
    s = sm[0]; q = sm[1];
}

__device__ __forceinline__ float lrelu(float v) { return v < 0.f ? 0.01f*v : v; }

// ---------------- zero stats ----------------
__global__ void k_zero() {
    int t = blockIdx.x*256 + threadIdx.x;
    if (t < 16*64) { g_statS[t] = 0.0; g_statQ[t] = 0.0; }
    if (t < 210)   { g_x2s[t] = 0.0;  g_x2q[t] = 0.0; }
}

// ---------------- weight prep: fp16, reorder to [l2k][co][k] ----------------
__global__ void k_wprep(const float* __restrict__ rw) {
    int i = blockIdx.x*256 + threadIdx.x;
    if (i >= 10*64*64*9) return;
    int tap = i % 9; int r = i / 9;
    int ci = r & 63; r >>= 6;
    int co = r & 63; int l2k = r >> 6;
    g_wswh[(l2k*64 + co)*576 + tap*64 + ci] = __float2half(rw[i]);
}

// ---------------- x_1d instance norm ----------------
__global__ void k1_norm1d(const float* __restrict__ x) {
    __shared__ float sm[32];
    int d = blockIdx.x;
    float v = x[d*384 + threadIdx.x];
    float s = v, q = v*v;
    blockReduce2(s, q, sm);
    float mu = s * (1.f/384.f);
    float var = q * (1.f/384.f) - mu*mu;
    float iv = rsqrtf(var + 1e-5f);
    g_x1n[d*384 + threadIdx.x] = (v - mu) * iv;
}

// ---------------- x_2d per-channel stats (float4) ----------------
__global__ void k2_x2stats(const float* __restrict__ x2) {
    __shared__ float sm[32];
    int c = blockIdx.y;
    const float4* p = (const float4*)(x2 + c*L2D + blockIdx.x*4096);
    float s = 0.f, q = 0.f;
    #pragma unroll
    for (int k = 0; k < 4; k++) {
        float4 v = p[threadIdx.x + k*256];
        s += v.x + v.y + v.z + v.w;
        q += v.x*v.x + v.y*v.y + v.z*v.z + v.w*v.w;
    }
    blockReduce2(s, q, sm);
    if (threadIdx.x == 0) {
        atomicAdd(&g_x2s[c], (double)s);
        atomicAdd(&g_x2q[c], (double)q);
    }
}

// ---------------- fold x2 norm into W2 (parallel over co) ----------------
__global__ void k2b_scaleW2(const float* __restrict__ W2) {
    __shared__ float smu[210], siv[210];
    __shared__ float sm[32];
    int t = threadIdx.x, co = blockIdx.x;
    if (t < 210) {
        float mu = (float)(g_x2s[t] * NPIX_INV);
        float var = (float)(g_x2q[t] * NPIX_INV) - mu*mu;
        smu[t] = mu; siv[t] = rsqrtf(var + 1e-5f);
    }
    __syncthreads();
    float a = 0.f;
    for (int d = t; d < 210; d += 256) {
        float w = W2[co*210 + d];
        g_W2s[co*210 + d] = w * siv[d];
        a += w * smu[d] * siv[d];
    }
    float dummy = 0.f;
    blockReduce2(a, dummy, sm);
    if (t == 0) g_c2[co] = -a;
}

// ---------------- row/col projections ----------------
__global__ void k3_rowcol(const float* __restrict__ W1) {
    int c = blockIdx.x >> 1, which = blockIdx.x & 1;
    const float* w = W1 + c*1576 + which*788;
    int l = threadIdx.x;
    float acc = 0.f;
    #pragma unroll 4
    for (int d = 0; d < 788; d++) acc += w[d] * g_x1n[d*384 + l];
    (which ? g_col : g_row)[c*384 + l] = acc;
}

// ---------------- pair1 separable stats ----------------
__global__ void k3b_pair1(const float* __restrict__ g1, const float* __restrict__ b1) {
    __shared__ float sm[32];
    int c = blockIdx.x, t = threadIdx.x;
    float sr = 0.f, qr = 0.f, sc_ = 0.f, qc = 0.f;
    for (int i = t; i < 384; i += 128) {
        float r = g_row[c*384+i]; sr += r; qr += r*r;
        float cl = g_col[c*384+i]; sc_ += cl; qc += cl*cl;
    }
    blockReduce2(sr, qr, sm);
    blockReduce2(sc_, qc, sm);
    float mur = sr*(1.f/384.f), muc = sc_*(1.f/384.f);
    float var = (qr*(1.f/384.f) - mur*mur) + (qc*(1.f/384.f) - muc*muc);
    float iv = rsqrtf(var + 1e-5f);
    float mu = mur + muc;
    float gc = g1[c], bc = b1[c];
    for (int i = t; i < 384; i += 128) {
        g_Ag[c*384+i] = gc*iv*(g_row[c*384+i] - mu) + bc;
        g_Bg[c*384+i] = gc*iv*g_col[c*384+i];
    }
}

// ---------------- pair2 = W2s @ x2 + c2 (stats idx 0) ----------------
__global__ void __launch_bounds__(256) k4_pair2(const float* __restrict__ x2) {
    __shared__ float s_w[32*210];
    __shared__ float s_red[8*32*2];
    int tid = threadIdx.x;
    int base = blockIdx.x * 512;
    int cb = blockIdx.y * 32;
    for (int i = tid; i < 32*210; i += 256) s_w[i] = g_W2s[cb*210 + i];
    __syncthreads();
    float a0[32], a1[32];
    #pragma unroll
    for (int i = 0; i < 32; i++) { a0[i] = 0.f; a1[i] = 0.f; }
    #pragma unroll 1
    for (int d = 0; d < 210; d++) {
        float v0 = x2[d*L2D + base + tid];
        float v1 = x2[d*L2D + base + tid + 256];
        #pragma unroll
        for (int co = 0; co < 32; co++) {
            float w = s_w[co*210 + d];
            a0[co] += w*v0; a1[co] += w*v1;
        }
    }
    int lane = tid & 31, w = tid >> 5;
    #pragma unroll
    for (int co = 0; co < 32; co++) {
        float cc = g_c2[cb+co];
        float v0 = a0[co] + cc, v1 = a1[co] + cc;
        g_bufP[(cb+co)*L2D + base + tid]       = v0;
        g_bufP[(cb+co)*L2D + base + tid + 256] = v1;
        float s = v0 + v1, q = v0*v0 + v1*v1;
        #pragma unroll
        for (int o = 16; o; o >>= 1) {
            s += __shfl_down_sync(0xffffffffu, s, o);
            q += __shfl_down_sync(0xffffffffu, q, o);
        }
        if (lane == 0) { s_red[(w*32+co)*2] = s; s_red[(w*32+co)*2+1] = q; }
    }
    __syncthreads();
    if (tid < 32) {
        float s = 0.f, q = 0.f;
        for (int i = 0; i < 8; i++) { s += s_red[(i*32+tid)*2]; q += s_red[(i*32+tid)*2+1]; }
        atomicAdd(&g_statS[cb+tid], (double)s);
        atomicAdd(&g_statQ[cb+tid], (double)q);
    }
}

// ---------------- finalize stats (atomic path, idx 0/1) ----------------
__global__ void k_fin(int idx, const float* __restrict__ g, const float* __restrict__ b) {
    int c = threadIdx.x;
    float mu = (float)(g_statS[idx*64+c] * NPIX_INV);
    float var = (float)(g_statQ[idx*64+c] * NPIX_INV) - mu*mu;
    float iv = rsqrtf(var + 1e-5f);
    g_nsc[idx*64+c] = g[c]*iv;
    g_nsh[idx*64+c] = b[c] - g[c]*iv*mu;
}

// ---------------- finalize stats from conv partials ----------------
__global__ void k_finred(int idx, const float* __restrict__ g, const float* __restrict__ b) {
    __shared__ float sm[32];
    int ch = blockIdx.x;
    float s = 0.f, q = 0.f;
    for (int i = threadIdx.x; i < 1152; i += 256) {
        s += g_pS[ch*1152 + i];
        q += g_pQ[ch*1152 + i];
    }
    blockReduce2(s, q, sm);
    if (threadIdx.x == 0) {
        float mu = s * (float)NPIX_INV;
        float var = q * (float)NPIX_INV - mu*mu;
        float iv = rsqrtf(var + 1e-5f);
        g_nsc[idx*64+ch] = g[ch]*iv;
        g_nsh[idx*64+ch] = b[ch] - g[ch]*iv*mu;
    }
}

// ---------------- mix (stats idx 1) ----------------
__global__ void __launch_bounds__(256) k5_mix(const float* __restrict__ W3) {
    __shared__ float s_w3[64*128];
    __shared__ float s_red[8*64*2];
    __shared__ float s_a[64], s_b[64];
    int tid = threadIdx.x;
    for (int i = tid; i < 64*128; i += 256) s_w3[i] = W3[i];
    if (tid < 64) { s_a[tid] = g_nsc[tid]; s_b[tid] = g_nsh[tid]; }
    __syncthreads();
    int pix = blockIdx.x*256 + tid;
    int i = pix / 384, j = pix - i*384;
    float acc[64];
    #pragma unroll
    for (int c = 0; c < 64; c++) acc[c] = 0.f;
    #pragma unroll 1
    for (int c = 0; c < 64; c++) {
        float p2 = g_bufP[c*L2D + pix];
        p2 = lrelu(s_a[c]*p2 + s_b[c]);
        float p1 = lrelu(g_Ag[c*384+i] + g_Bg[c*384+j]);
        #pragma unroll
        for (int co = 0; co < 64; co++)
            acc[co] += s_w3[co*128 + c]*p1 + s_w3[co*128 + 64 + c]*p2;
    }
    int lane = tid & 31, w = tid >> 5;
    #pragma unroll
    for (int co = 0; co < 64; co++) {
        float v = acc[co];
        g_bufR[co*L2D + pix] = v;
        float s = v, q = v*v;
        #pragma unroll
        for (int o = 16; o; o >>= 1) {
            s += __shfl_down_sync(0xffffffffu, s, o);
            q += __shfl_down_sync(0xffffffffu, q, o);
        }
        if (lane == 0) { s_red[(w*64+co)*2] = s; s_red[(w*64+co)*2+1] = q; }
    }
    __syncthreads();
    if (tid < 64) {
        float s = 0.f, q = 0.f;
        for (int k = 0; k < 8; k++) { s += s_red[(k*64+tid)*2]; q += s_red[(k*64+tid)*2+1]; }
        atomicAdd(&g_statS[64+tid], (double)s);
        atomicAdd(&g_statQ[64+tid], (double)q);
    }
}

// ---------------- normalize + leaky (+ residual), float4 ----------------
__global__ void k_apply4(const float4* __restrict__ raw, int idx,
                         const float4* __restrict__ res, float4* __restrict__ out) {
    int i = blockIdx.x*256 + threadIdx.x;
    int c = i / (L2D/4);
    float sc = g_nsc[idx*64+c], sh = g_nsh[idx*64+c];
    float4 v = raw[i];
    v.x = lrelu(v.x*sc + sh);
    v.y = lrelu(v.y*sc + sh);
    v.z = lrelu(v.z*sc + sh);
    v.w = lrelu(v.w*sc + sh);
    if (res) {
        float4 r = res[i];
        v.x += r.x; v.y += r.y; v.z += r.z; v.w += r.w;
    }
    out[i] = v;
}

// ================= fp16 m16n8k16 implicit-GEMM conv =================
// CTA: 128 px x 64 cout.  K = 576 in 9 chunks of 64 (one tap each).
// A smem [128px][64k] half, row 144B; W smem [64co][64k] half, row 144B.
// Double-buffered, one __syncthreads per chunk. STS.128 staging conflict-free.
#define A_STRIDE_H 72
#define W_STRIDE_H 72
#define CONV_SMEM ((2*128*A_STRIDE_H + 2*64*W_STRIDE_H)*2)

template<bool APPLY>
__global__ void __launch_bounds__(256, 2)
conv_mma(const float* __restrict__ in, int aidx, const __half* __restrict__ wsrc,
         int D, const float* __restrict__ bias, float* __restrict__ out)
{
    extern __shared__ __half smh[];
    __half* sA = smh;                          // 2 * 128*72 half
    __half* sW = smh + 2*128*A_STRIDE_H;       // 2 * 64*72 half
    __shared__ float s_bias[64];
    __shared__ float s_nsc[64], s_nsh[64];
    __shared__ float s_rs[8][4][8], s_rq[8][4][8];

    int tid = threadIdx.x, lane = tid & 31, wid = tid >> 5;
    int x0 = blockIdx.x * 128, y = blockIdx.y;
    int cta = blockIdx.y * 3 + blockIdx.x;
    int wm = wid & 3, wn = wid >> 2;
    int rA = lane >> 2, qA = lane & 3;

    if (tid < 64) {
        s_bias[tid] = bias[tid];
        if (APPLY) { s_nsc[tid] = g_nsc[aidx*64 + tid]; s_nsh[tid] = g_nsh[aidx*64 + tid]; }
    }
    if (APPLY) __syncthreads();   // gather needs s_nsc/s_nsh

    float acc[2][4][4];
    #pragma unroll
    for (int mt = 0; mt < 2; mt++)
        #pragma unroll
        for (int nt = 0; nt < 4; nt++)
            #pragma unroll
            for (int r = 0; r < 4; r++) acc[mt][nt][r] = 0.f;

    uint4 stg[4];
    uint4 wstg[2];

    // gather one tap: 128px x 64ci, convert to half
    auto ldchunk = [&](int tap) {
        int dy = (tap/3 - 1)*D, dx = (tap%3 - 1)*D;
        int gy = y + dy;
        bool gyok = ((unsigned)gy < 384u);
        const float* ip = in + gy*IMG;
        #pragma unroll
        for (int r = 0; r < 4; r++) {
            int e = tid + r*256;                // 1024 units of 8 halves
            int px = e & 127, kg = e >> 7;      // kg = 8-ci group (0..7)
            int gx = x0 + px + dx;
            uint4 v = make_uint4(0u, 0u, 0u, 0u);
            if (gyok && (unsigned)gx < 384u) {
                int cb = kg*8;
                const float* p = ip + cb*L2D + gx;
                float f0 = p[0],       f1 = p[L2D],     f2 = p[2*L2D], f3 = p[3*L2D];
                float f4 = p[4*L2D],   f5 = p[5*L2D],   f6 = p[6*L2D], f7 = p[7*L2D];
                if (APPLY) {
                    f0 = lrelu(f0*s_nsc[cb]   + s_nsh[cb]);
                    f1 = lrelu(f1*s_nsc[cb+1] + s_nsh[cb+1]);
                    f2 = lrelu(f2*s_nsc[cb+2] + s_nsh[cb+2]);
                    f3 = lrelu(f3*s_nsc[cb+3] + s_nsh[cb+3]);
                    f4 = lrelu(f4*s_nsc[cb+4] + s_nsh[cb+4]);
                    f5 = lrelu(f5*s_nsc[cb+5] + s_nsh[cb+5]);
                    f6 = lrelu(f6*s_nsc[cb+6] + s_nsh[cb+6]);
                    f7 = lrelu(f7*s_nsc[cb+7] + s_nsh[cb+7]);
                }
                __half2 h0 = __floats2half2_rn(f0, f1);
                __half2 h1 = __floats2half2_rn(f2, f3);
                __half2 h2 = __floats2half2_rn(f4, f5);
                __half2 h3 = __floats2half2_rn(f6, f7);
                v.x = *(uint32_t*)&h0; v.y = *(uint32_t*)&h1;
                v.z = *(uint32_t*)&h2; v.w = *(uint32_t*)&h3;
            }
            stg[r] = v;
        }
    };
    auto stchunk = [&](int b) {
        char* abuf = (char*)(sA + b*128*A_STRIDE_H);
        #pragma unroll
        for (int r = 0; r < 4; r++) {
            int e = tid + r*256;
            int px = e & 127, kg = e >> 7;
            *(uint4*)(abuf + px*144 + kg*16) = stg[r];
        }
    };
    auto ldw = [&](int tap) {
        const uint4* ps = (const uint4*)(wsrc + (tid>>2)*576 + tap*64 + (tid&3)*16);
        wstg[0] = ps[0];
        wstg[1] = ps[1];
    };
    auto stw = [&](int b) {
        char* wb = (char*)(sW + b*64*W_STRIDE_H) + (tid>>2)*144 + (tid&3)*32;
        *(uint4*)wb = wstg[0];
        *((uint4*)wb + 1) = wstg[1];
    };

    ldchunk(0); ldw(0);
    stchunk(0); stw(0);
    __syncthreads();

    #pragma unroll 1
    for (int c = 0; c < 9; c++) {
        int b = c & 1;
        if (c + 1 < 9) { ldchunk(c + 1); ldw(c + 1); }   // global loads in flight

        const uint32_t* Ab = (const uint32_t*)(sA + b*128*A_STRIDE_H);
        const uint32_t* Bb = (const uint32_t*)(sW + b*64*W_STRIDE_H);
        #pragma unroll
        for (int ks = 0; ks < 4; ks++) {
            uint32_t a[2][4];
            #pragma unroll
            for (int mt = 0; mt < 2; mt++) {
                const uint32_t* Ap = Ab + (wm*32 + mt*16 + rA)*36 + ks*8 + qA;
                a[mt][0] = Ap[0];
                a[mt][1] = Ap[8*36];
                a[mt][2] = Ap[4];
                a[mt][3] = Ap[8*36 + 4];
            }
            uint32_t bf[4][2];
            #pragma unroll
            for (int nt = 0; nt < 4; nt++) {
                const uint32_t* Bp = Bb + (wn*32 + nt*8 + rA)*36 + ks*8 + qA;
                bf[nt][0] = Bp[0];
                bf[nt][1] = Bp[4];
            }
            #pragma unroll
            for (int mt = 0; mt < 2; mt++)
                #pragma unroll
                for (int nt = 0; nt < 4; nt++)
                    mma_f16_16n8k16(acc[mt][nt], a[mt], bf[nt]);
        }
        // store next chunk into the other buffer: its readers finished before
        // the sync at the end of the previous iteration -> one sync per chunk.
        if (c + 1 < 9) { stchunk(b ^ 1); stw(b ^ 1); }
        __syncthreads();
    }

    // ---- epilogue: bias + store raw + per-channel partial stats ----
    float ss[4][2], qq[4][2];
    #pragma unroll
    for (int nt = 0; nt < 4; nt++) { ss[nt][0]=0.f; ss[nt][1]=0.f; qq[nt][0]=0.f; qq[nt][1]=0.f; }
    int gbase = y*IMG + x0 + wm*32;
    #pragma unroll
    for (int nt = 0; nt < 4; nt++) {
        int coA = wn*32 + nt*8 + 2*qA;
        float bA = s_bias[coA], bB = s_bias[coA+1];
        #pragma unroll
        for (int mt = 0; mt < 2; mt++) {
            int px = gbase + mt*16 + rA;
            float v0 = acc[mt][nt][0] + bA;
            float v1 = acc[mt][nt][1] + bB;
            float v2 = acc[mt][nt][2] + bA;
            float v3 = acc[mt][nt][3] + bB;
            out[coA*L2D + px]         = v0;
            out[(coA+1)*L2D + px]     = v1;
            out[coA*L2D + px + 8]     = v2;
            out[(coA+1)*L2D + px + 8] = v3;
            ss[nt][0] += v0 + v2;  qq[nt][0] += v0*v0 + v2*v2;
            ss[nt][1] += v1 + v3;  qq[nt][1] += v1*v1 + v3*v3;
        }
    }
    #pragma unroll
    for (int nt = 0; nt < 4; nt++)
        #pragma unroll
        for (int e = 0; e < 2; e++) {
            float s = ss[nt][e], q = qq[nt][e];
            s += __shfl_down_sync(0xffffffffu, s, 16);
            q += __shfl_down_sync(0xffffffffu, q, 16);
            s += __shfl_down_sync(0xffffffffu, s, 8);
            q += __shfl_down_sync(0xffffffffu, q, 8);
            s += __shfl_down_sync(0xffffffffu, s, 4);
            q += __shfl_down_sync(0xffffffffu, q, 4);
            ss[nt][e] = s; qq[nt][e] = q;
        }
    if (lane < 4) {
        #pragma unroll
        for (int nt = 0; nt < 4; nt++) {
            s_rs[wid][lane][nt*2]   = ss[nt][0];  s_rq[wid][lane][nt*2]   = qq[nt][0];
            s_rs[wid][lane][nt*2+1] = ss[nt][1];  s_rq[wid][lane][nt*2+1] = qq[nt][1];
        }
    }
    __syncthreads();
    if (tid < 64) {
        int wn2 = tid >> 5, rem = tid & 31;
        int nt = rem >> 3, low = rem & 7, qa2 = low >> 1, e = low & 1;
        float s = 0.f, q = 0.f;
        #pragma unroll
        for (int wm2 = 0; wm2 < 4; wm2++) {
            s += s_rs[wn2*4 + wm2][qa2][nt*2 + e];
            q += s_rq[wn2*4 + wm2][qa2][nt*2 + e];
        }
        g_pS[tid*1152 + cta] = s;
        g_pQ[tid*1152 + cta] = q;
    }
}

// ---------------- launch ----------------
extern "C" void kernel_launch(void* const* d_in, const int* in_sizes, int n_in,
                              void* d_out, int out_size) {
    const float* x1d  = (const float*)d_in[0];
    const float* x2   = (const float*)d_in[1];
    const float* W1   = (const float*)d_in[2];
    const float* g1   = (const float*)d_in[3];
    const float* b1   = (const float*)d_in[4];
    const float* W2   = (const float*)d_in[5];
    const float* g2   = (const float*)d_in[6];
    const float* b2   = (const float*)d_in[7];
    const float* W3   = (const float*)d_in[8];
    const float* g3   = (const float*)d_in[9];
    const float* b3   = (const float*)d_in[10];
    const float* rw   = (const float*)d_in[11];
    const float* rb   = (const float*)d_in[12];
    const float* rg   = (const float*)d_in[13];
    const float* rbe  = (const float*)d_in[14];
    float* out = (float*)d_out;

    float *bP, *bR, *bX, *bT;
    __half* wh;
    cudaGetSymbolAddress((void**)&bP, g_bufP);
    cudaGetSymbolAddress((void**)&bR, g_bufR);
    cudaGetSymbolAddress((void**)&bX, g_bufX);
    cudaGetSymbolAddress((void**)&bT, g_bufT);
    cudaGetSymbolAddress((void**)&wh, g_wswh);

    cudaFuncSetAttribute(conv_mma<false>, cudaFuncAttributeMaxDynamicSharedMemorySize, CONV_SMEM);
    cudaFuncSetAttribute(conv_mma<true>,  cudaFuncAttributeMaxDynamicSharedMemorySize, CONV_SMEM);

    dim3 cgrid(3, 384);

    k_zero<<<4, 256>>>();                                       // #1
    k_wprep<<<1440, 256>>>(rw);                                 // #2
    k1_norm1d<<<788, 384>>>(x1d);                               // #3
    // #4: DIAGNOSTIC conv (ncu empirically captures launch #4). Reads stale
    // scratch (deterministic per-replay), writes bR which k5_mix overwrites
    // before any consumer -> final output unaffected. Remove next round.
    conv_mma<false><<<cgrid, 256, CONV_SMEM>>>(bX, 0, wh, 1, rb, bR);
    k2_x2stats<<<dim3(36, 210), 256>>>(x2);                     // #5
    k2b_scaleW2<<<64, 256>>>(W2);
    k3_rowcol<<<128, 384>>>(W1);
    k3b_pair1<<<64, 128>>>(g1, b1);
    k4_pair2<<<dim3(288, 2), 256>>>(x2);
    k_fin<<<1, 64>>>(0, g2, b2);
    k5_mix<<<576, 256>>>(W3);
    k_fin<<<1, 64>>>(1, g3, b3);
    k_apply4<<<9216, 256>>>((const float4*)bR, 1, nullptr, (float4*)bX);

    float* cur = bX;
    float* other = bP;
    const int DIL[5] = {1, 2, 4, 2, 1};
    for (int l = 0; l < 5; l++) {
        int D = DIL[l];
        int si0 = 2 + l*2, si1 = si0 + 1;
        conv_mma<false><<<cgrid, 256, CONV_SMEM>>>(cur, 0, wh + (l*2)*36864, D,
                                                   rb + (l*2)*64, bR);
        k_finred<<<64, 256>>>(si0, rg + (l*2)*64, rbe + (l*2)*64);
        conv_mma<true><<<cgrid, 256, CONV_SMEM>>>(bR, si0, wh + (l*2+1)*36864, D,
                                                  rb + (l*2+1)*64, bT);
        k_finred<<<64, 256>>>(si1, rg + (l*2+1)*64, rbe + (l*2+1)*64);
        float* dst = (l == 4) ? out : other;
        k_apply4<<<9216, 256>>>((const float4*)bT, si1, (const float4*)cur, (float4*)dst);
        if (l < 4) { float* tmp = cur; cur = other; other = tmp; }
    }
}

// round 12
// speedup vs baseline: 4.0646x; 1.2468x over previous
#include <cuda_runtime.h>
#include <cuda_fp16.h>
#include <cstdint>

#define L2D 147456   // 384*384
#define IMG 384
#define NPIX_INV (1.0/147456.0)

// ---------------- static scratch ----------------
__device__ float g_x1n[788*384];
__device__ float g_row[64*384];
__device__ float g_col[64*384];
__device__ float g_Ag[64*384];
__device__ float g_Bg[64*384];
__device__ float g_W2s[64*210];
__device__ float g_c2[64];
__device__ double g_x2s[210];
__device__ double g_x2q[210];
__device__ double g_statS[2*64];
__device__ double g_statQ[2*64];
__device__ float g_nsc[16*64];
__device__ float g_nsh[16*64];

__device__ __half g_wswh[10*64*576];   // fp16 conv weights, [l2k][co][k = tap*64 + ci]
__device__ __half g_w3h[64*128];       // fp16 mix weights, [co][k]
__device__ float g_pS[64*1152];        // per-CTA partial sums (deterministic)
__device__ float g_pQ[64*1152];

__device__ float g_bufP[64*L2D];
__device__ float g_bufR[64*L2D];
__device__ float g_bufX[64*L2D];
__device__ float g_bufT[64*L2D];

// ---------------- helpers ----------------
__device__ __forceinline__ uint32_t smem_u32(const void* p){
    uint32_t a;
    asm("{ .reg .u64 t; cvta.to.shared.u64 t, %1; cvt.u32.u64 %0, t; }" : "=r"(a) : "l"(p));
    return a;
}
__device__ __forceinline__ void mma_f16_16n8k16(float* c, const uint32_t* a, const uint32_t* b){
    asm volatile("mma.sync.aligned.m16n8k16.row.col.f32.f16.f16.f32 "
        "{%0,%1,%2,%3}, {%4,%5,%6,%7}, {%8,%9}, {%0,%1,%2,%3};"
        : "+f"(c[0]), "+f"(c[1]), "+f"(c[2]), "+f"(c[3])
        : "r"(a[0]), "r"(a[1]), "r"(a[2]), "r"(a[3]), "r"(b[0]), "r"(b[1]));
}
__device__ __forceinline__ void ldsm_x4(uint32_t& r0, uint32_t& r1, uint32_t& r2, uint32_t& r3,
                                        uint32_t addr){
    asm volatile("ldmatrix.sync.aligned.m8n8.x4.shared.b16 {%0,%1,%2,%3}, [%4];"
        : "=r"(r0), "=r"(r1), "=r"(r2), "=r"(r3) : "r"(addr));
}

__device__ __forceinline__ void blockReduce2(float& s, float& q, float* sm) {
    __syncthreads();
    int lane = threadIdx.x & 31, w = threadIdx.x >> 5;
    #pragma unroll
    for (int o = 16; o; o >>= 1) {
        s += __shfl_down_sync(0xffffffffu, s, o);
        q += __shfl_down_sync(0xffffffffu, q, o);
    }
    if (lane == 0) { sm[2*w] = s; sm[2*w+1] = q; }
    __syncthreads();
    int nw = blockDim.x >> 5;
    if (threadIdx.x == 0) {
        float S = 0.f, Q = 0.f;
        for (int i = 0; i < nw; i++) { S += sm[2*i]; Q += sm[2*i+1]; }
        sm[0] = S; sm[1] = Q;
    }
    __syncthreads();
    s = sm[0]; q = sm[1];
}

__device__ __forceinline__ float lrelu(float v) { return v < 0.f ? 0.01f*v : v; }

// ---------------- zero stats ----------------
__global__ void k_zero() {
    int t = blockIdx.x*256 + threadIdx.x;
    if (t < 2*64) { g_statS[t] = 0.0; g_statQ[t] = 0.0; }
    if (t < 210)  { g_x2s[t] = 0.0;  g_x2q[t] = 0.0; }
}

// ---------------- weight prep ----------------
__global__ void k_wprep(const float* __restrict__ rw) {
    int i = blockIdx.x*256 + threadIdx.x;
    if (i >= 10*64*64*9) return;
    int tap = i % 9; int r = i / 9;
    int ci = r & 63; r >>= 6;
    int co = r & 63; int l2k = r >> 6;
    g_wswh[(l2k*64 + co)*576 + tap*64 + ci] = __float2half(rw[i]);
}
__global__ void k_w3prep(const float* __restrict__ W3) {
    int i = blockIdx.x*256 + threadIdx.x;   // 8192
    g_w3h[i] = __float2half(W3[i]);
}

// ---------------- x_1d instance norm ----------------
__global__ void k1_norm1d(const float* __restrict__ x) {
    __shared__ float sm[32];
    int d = blockIdx.x;
    float v = x[d*384 + threadIdx.x];
    float s = v, q = v*v;
    blockReduce2(s, q, sm);
    float mu = s * (1.f/384.f);
    float var = q * (1.f/384.f) - mu*mu;
    float iv = rsqrtf(var + 1e-5f);
    g_x1n[d*384 + threadIdx.x] = (v - mu) * iv;
}

// ---------------- x_2d per-channel stats (float4) ----------------
__global__ void k2_x2stats(const float* __restrict__ x2) {
    __shared__ float sm[32];
    int c = blockIdx.y;
    const float4* p = (const float4*)(x2 + c*L2D + blockIdx.x*4096);
    float s = 0.f, q = 0.f;
    #pragma unroll
    for (int k = 0; k < 4; k++) {
        float4 v = p[threadIdx.x + k*256];
        s += v.x + v.y + v.z + v.w;
        q += v.x*v.x + v.y*v.y + v.z*v.z + v.w*v.w;
    }
    blockReduce2(s, q, sm);
    if (threadIdx.x == 0) {
        atomicAdd(&g_x2s[c], (double)s);
        atomicAdd(&g_x2q[c], (double)q);
    }
}

// ---------------- fold x2 norm into W2 (parallel over co) ----------------
__global__ void k2b_scaleW2(const float* __restrict__ W2) {
    __shared__ float smu[210], siv[210];
    __shared__ float sm[32];
    int t = threadIdx.x, co = blockIdx.x;
    if (t < 210) {
        float mu = (float)(g_x2s[t] * NPIX_INV);
        float var = (float)(g_x2q[t] * NPIX_INV) - mu*mu;
        smu[t] = mu; siv[t] = rsqrtf(var + 1e-5f);
    }
    __syncthreads();
    float a = 0.f;
    for (int d = t; d < 210; d += 256) {
        float w = W2[co*210 + d];
        g_W2s[co*210 + d] = w * siv[d];
        a += w * smu[d] * siv[d];
    }
    float dummy = 0.f;
    blockReduce2(a, dummy, sm);
    if (t == 0) g_c2[co] = -a;
}

// ---------------- row/col projections ----------------
__global__ void k3_rowcol(const float* __restrict__ W1) {
    int c = blockIdx.x >> 1, which = blockIdx.x & 1;
    const float* w = W1 + c*1576 + which*788;
    int l = threadIdx.x;
    float acc = 0.f;
    #pragma unroll 4
    for (int d = 0; d < 788; d++) acc += w[d] * g_x1n[d*384 + l];
    (which ? g_col : g_row)[c*384 + l] = acc;
}

// ---------------- pair1 separable stats ----------------
__global__ void k3b_pair1(const float* __restrict__ g1, const float* __restrict__ b1) {
    __shared__ float sm[32];
    int c = blockIdx.x, t = threadIdx.x;
    float sr = 0.f, qr = 0.f, sc_ = 0.f, qc = 0.f;
    for (int i = t; i < 384; i += 128) {
        float r = g_row[c*384+i]; sr += r; qr += r*r;
        float cl = g_col[c*384+i]; sc_ += cl; qc += cl*cl;
    }
    blockReduce2(sr, qr, sm);
    blockReduce2(sc_, qc, sm);
    float mur = sr*(1.f/384.f), muc = sc_*(1.f/384.f);
    float var = (qr*(1.f/384.f) - mur*mur) + (qc*(1.f/384.f) - muc*muc);
    float iv = rsqrtf(var + 1e-5f);
    float mu = mur + muc;
    float gc = g1[c], bc = b1[c];
    for (int i = t; i < 384; i += 128) {
        g_Ag[c*384+i] = gc*iv*(g_row[c*384+i] - mu) + bc;
        g_Bg[c*384+i] = gc*iv*g_col[c*384+i];
    }
}

// ---------------- pair2 = W2s @ x2 + c2 (stats idx 0) ----------------
__global__ void __launch_bounds__(256) k4_pair2(const float* __restrict__ x2) {
    __shared__ float s_w[32*210];
    __shared__ float s_red[8*32*2];
    int tid = threadIdx.x;
    int base = blockIdx.x * 512;
    int cb = blockIdx.y * 32;
    for (int i = tid; i < 32*210; i += 256) s_w[i] = g_W2s[cb*210 + i];
    __syncthreads();
    float a0[32], a1[32];
    #pragma unroll
    for (int i = 0; i < 32; i++) { a0[i] = 0.f; a1[i] = 0.f; }
    #pragma unroll 1
    for (int d = 0; d < 210; d++) {
        float v0 = x2[d*L2D + base + tid];
        float v1 = x2[d*L2D + base + tid + 256];
        #pragma unroll
        for (int co = 0; co < 32; co++) {
            float w = s_w[co*210 + d];
            a0[co] += w*v0; a1[co] += w*v1;
        }
    }
    int lane = tid & 31, w = tid >> 5;
    #pragma unroll
    for (int co = 0; co < 32; co++) {
        float cc = g_c2[cb+co];
        float v0 = a0[co] + cc, v1 = a1[co] + cc;
        g_bufP[(cb+co)*L2D + base + tid]       = v0;
        g_bufP[(cb+co)*L2D + base + tid + 256] = v1;
        float s = v0 + v1, q = v0*v0 + v1*v1;
        #pragma unroll
        for (int o = 16; o; o >>= 1) {
            s += __shfl_down_sync(0xffffffffu, s, o);
            q += __shfl_down_sync(0xffffffffu, q, o);
        }
        if (lane == 0) { s_red[(w*32+co)*2] = s; s_red[(w*32+co)*2+1] = q; }
    }
    __syncthreads();
    if (tid < 32) {
        float s = 0.f, q = 0.f;
        for (int i = 0; i < 8; i++) { s += s_red[(i*32+tid)*2]; q += s_red[(i*32+tid)*2+1]; }
        atomicAdd(&g_statS[cb+tid], (double)s);
        atomicAdd(&g_statQ[cb+tid], (double)q);
    }
}

// ---------------- finalize stats (atomic path, idx 0) ----------------
__global__ void k_fin(int idx, const float* __restrict__ g, const float* __restrict__ b) {
    int c = threadIdx.x;
    float mu = (float)(g_statS[idx*64+c] * NPIX_INV);
    float var = (float)(g_statQ[idx*64+c] * NPIX_INV) - mu*mu;
    float iv = rsqrtf(var + 1e-5f);
    g_nsc[idx*64+c] = g[c]*iv;
    g_nsh[idx*64+c] = b[c] - g[c]*iv*mu;
}

// ---------------- finalize stats from per-CTA partials ----------------
__global__ void k_finred(int idx, const float* __restrict__ g, const float* __restrict__ b) {
    __shared__ float sm[32];
    int ch = blockIdx.x;
    float s = 0.f, q = 0.f;
    for (int i = threadIdx.x; i < 1152; i += 256) {
        s += g_pS[ch*1152 + i];
        q += g_pQ[ch*1152 + i];
    }
    blockReduce2(s, q, sm);
    if (threadIdx.x == 0) {
        float mu = s * (float)NPIX_INV;
        float var = q * (float)NPIX_INV - mu*mu;
        float iv = rsqrtf(var + 1e-5f);
        g_nsc[idx*64+ch] = g[ch]*iv;
        g_nsh[idx*64+ch] = b[ch] - g[ch]*iv*mu;
    }
}

// ---------------- normalize + leaky (+ residual), float4 ----------------
__global__ void k_apply4(const float4* __restrict__ raw, int idx,
                         const float4* __restrict__ res, float4* __restrict__ out) {
    int i = blockIdx.x*256 + threadIdx.x;
    int c = i / (L2D/4);
    float sc = g_nsc[idx*64+c], sh = g_nsh[idx*64+c];
    float4 v = raw[i];
    v.x = lrelu(v.x*sc + sh);
    v.y = lrelu(v.y*sc + sh);
    v.z = lrelu(v.z*sc + sh);
    v.w = lrelu(v.w*sc + sh);
    if (res) {
        float4 r = res[i];
        v.x += r.x; v.y += r.y; v.z += r.z; v.w += r.w;
    }
    out[i] = v;
}

// ---- shared epilogue: bias + store raw + per-channel partial stats ----
struct EpiSmem { float rs[8][4][8]; float rq[8][4][8]; };

__device__ __forceinline__ void conv_epilogue(
    float acc[2][4][4], const float* s_bias, EpiSmem* es,
    int wm, int wn, int wid, int lane, int rA, int qA,
    int y, int x0, int cta, float* __restrict__ out)
{
    float ss[4][2], qq[4][2];
    #pragma unroll
    for (int nt = 0; nt < 4; nt++) { ss[nt][0]=0.f; ss[nt][1]=0.f; qq[nt][0]=0.f; qq[nt][1]=0.f; }
    int gbase = y*IMG + x0 + wm*32;
    #pragma unroll
    for (int nt = 0; nt < 4; nt++) {
        int coA = wn*32 + nt*8 + 2*qA;
        float bA = s_bias ? s_bias[coA] : 0.f;
        float bB = s_bias ? s_bias[coA+1] : 0.f;
        #pragma unroll
        for (int mt = 0; mt < 2; mt++) {
            int px = gbase + mt*16 + rA;
            float v0 = acc[mt][nt][0] + bA;
            float v1 = acc[mt][nt][1] + bB;
            float v2 = acc[mt][nt][2] + bA;
            float v3 = acc[mt][nt][3] + bB;
            out[coA*L2D + px]         = v0;
            out[(coA+1)*L2D + px]     = v1;
            out[coA*L2D + px + 8]     = v2;
            out[(coA+1)*L2D + px + 8] = v3;
            ss[nt][0] += v0 + v2;  qq[nt][0] += v0*v0 + v2*v2;
            ss[nt][1] += v1 + v3;  qq[nt][1] += v1*v1 + v3*v3;
        }
    }
    #pragma unroll
    for (int nt = 0; nt < 4; nt++)
        #pragma unroll
        for (int e = 0; e < 2; e++) {
            float s = ss[nt][e], q = qq[nt][e];
            s += __shfl_down_sync(0xffffffffu, s, 16);
            q += __shfl_down_sync(0xffffffffu, q, 16);
            s += __shfl_down_sync(0xffffffffu, s, 8);
            q += __shfl_down_sync(0xffffffffu, q, 8);
            s += __shfl_down_sync(0xffffffffu, s, 4);
            q += __shfl_down_sync(0xffffffffu, q, 4);
            ss[nt][e] = s; qq[nt][e] = q;
        }
    if (lane < 4) {
        #pragma unroll
        for (int nt = 0; nt < 4; nt++) {
            es->rs[wid][lane][nt*2]   = ss[nt][0];  es->rq[wid][lane][nt*2]   = qq[nt][0];
            es->rs[wid][lane][nt*2+1] = ss[nt][1];  es->rq[wid][lane][nt*2+1] = qq[nt][1];
        }
    }
    __syncthreads();
    int tid = threadIdx.x;
    if (tid < 64) {
        int wn2 = tid >> 5, rem = tid & 31;
        int nt = rem >> 3, low = rem & 7, qa2 = low >> 1, e = low & 1;
        float s = 0.f, q = 0.f;
        #pragma unroll
        for (int wm2 = 0; wm2 < 4; wm2++) {
            s += es->rs[wn2*4 + wm2][qa2][nt*2 + e];
            q += es->rq[wn2*4 + wm2][qa2][nt*2 + e];
        }
        g_pS[tid*1152 + cta] = s;
        g_pQ[tid*1152 + cta] = q;
    }
}

// ================= fp16 m16n8k16 implicit-GEMM conv (ldmatrix) =================
// CTA: 128 px x 64 cout.  K = 576 in 9 chunks of 64 (one tap each).
// A smem [128px][64k] half row 144B; W smem [64co][64k] half row 144B. ldmatrix frags.
#define A_STRIDE_H 72
#define W_STRIDE_H 72
#define CONV_SMEM ((2*128*A_STRIDE_H + 2*64*W_STRIDE_H)*2)

template<bool APPLY>
__global__ void __launch_bounds__(256, 2)
conv_mma(const float* __restrict__ in, int aidx, const __half* __restrict__ wsrc,
         int D, const float* __restrict__ bias, float* __restrict__ out)
{
    extern __shared__ __half smh[];
    __half* sA = smh;                          // 2 * 128*72 half
    __half* sW = smh + 2*128*A_STRIDE_H;       // 2 * 64*72 half
    __shared__ float s_bias[64];
    __shared__ float s_nsc[64], s_nsh[64];
    __shared__ EpiSmem es;

    int tid = threadIdx.x, lane = tid & 31, wid = tid >> 5;
    int x0 = blockIdx.x * 128, y = blockIdx.y;
    int cta = blockIdx.y * 3 + blockIdx.x;
    int wm = wid & 3, wn = wid >> 2;
    int rA = lane >> 2, qA = lane & 3;

    if (tid < 64) {
        s_bias[tid] = bias[tid];
        if (APPLY) { s_nsc[tid] = g_nsc[aidx*64 + tid]; s_nsh[tid] = g_nsh[aidx*64 + tid]; }
    }
    if (APPLY) __syncthreads();

    float acc[2][4][4];
    #pragma unroll
    for (int mt = 0; mt < 2; mt++)
        #pragma unroll
        for (int nt = 0; nt < 4; nt++)
            #pragma unroll
            for (int r = 0; r < 4; r++) acc[mt][nt][r] = 0.f;

    uint4 stg[4];
    uint4 wstg[2];

    auto ldchunk = [&](int tap) {
        int dy = (tap/3 - 1)*D, dx = (tap%3 - 1)*D;
        int gy = y + dy;
        bool gyok = ((unsigned)gy < 384u);
        const float* ip = in + gy*IMG;
        #pragma unroll
        for (int r = 0; r < 4; r++) {
            int e = tid + r*256;
            int px = e & 127, kg = e >> 7;
            int gx = x0 + px + dx;
            uint4 v = make_uint4(0u, 0u, 0u, 0u);
            if (gyok && (unsigned)gx < 384u) {
                int cb = kg*8;
                const float* p = ip + cb*L2D + gx;
                float f0 = p[0],     f1 = p[L2D],   f2 = p[2*L2D], f3 = p[3*L2D];
                float f4 = p[4*L2D], f5 = p[5*L2D], f6 = p[6*L2D], f7 = p[7*L2D];
                if (APPLY) {
                    f0 = lrelu(f0*s_nsc[cb]   + s_nsh[cb]);
                    f1 = lrelu(f1*s_nsc[cb+1] + s_nsh[cb+1]);
                    f2 = lrelu(f2*s_nsc[cb+2] + s_nsh[cb+2]);
                    f3 = lrelu(f3*s_nsc[cb+3] + s_nsh[cb+3]);
                    f4 = lrelu(f4*s_nsc[cb+4] + s_nsh[cb+4]);
                    f5 = lrelu(f5*s_nsc[cb+5] + s_nsh[cb+5]);
                    f6 = lrelu(f6*s_nsc[cb+6] + s_nsh[cb+6]);
                    f7 = lrelu(f7*s_nsc[cb+7] + s_nsh[cb+7]);
                }
                __half2 h0 = __floats2half2_rn(f0, f1);
                __half2 h1 = __floats2half2_rn(f2, f3);
                __half2 h2 = __floats2half2_rn(f4, f5);
                __half2 h3 = __floats2half2_rn(f6, f7);
                v.x = *(uint32_t*)&h0; v.y = *(uint32_t*)&h1;
                v.z = *(uint32_t*)&h2; v.w = *(uint32_t*)&h3;
            }
            stg[r] = v;
        }
    };
    auto stchunk = [&](int b) {
        char* abuf = (char*)(sA + b*128*A_STRIDE_H);
        #pragma unroll
        for (int r = 0; r < 4; r++) {
            int e = tid + r*256;
            int px = e & 127, kg = e >> 7;
            *(uint4*)(abuf + px*144 + kg*16) = stg[r];
        }
    };
    auto ldw = [&](int tap) {
        const uint4* ps = (const uint4*)(wsrc + (tid>>2)*576 + tap*64 + (tid&3)*16);
        wstg[0] = ps[0];
        wstg[1] = ps[1];
    };
    auto stw = [&](int b) {
        char* wb = (char*)(sW + b*64*W_STRIDE_H) + (tid>>2)*144 + (tid&3)*32;
        *(uint4*)wb = wstg[0];
        *((uint4*)wb + 1) = wstg[1];
    };

    ldchunk(0); ldw(0);
    stchunk(0); stw(0);
    __syncthreads();

    // ldmatrix lane-invariant address bases
    uint32_t aBase = smem_u32(sA) + (uint32_t)(((wm*32 + (lane & 15))*A_STRIDE_H
                    + ((lane >> 4) << 3)) * 2);
    uint32_t bBase = smem_u32(sW) + (uint32_t)(((wn*32 + (lane & 7) + ((lane >> 4) << 3))*W_STRIDE_H
                    + (lane & 8)) * 2);

    #pragma unroll 1
    for (int c = 0; c < 9; c++) {
        int b = c & 1;
        if (c + 1 < 9) { ldchunk(c + 1); ldw(c + 1); }

        uint32_t aOff = aBase + (uint32_t)(b*128*A_STRIDE_H*2);
        uint32_t bOff = bBase + (uint32_t)(b*64*W_STRIDE_H*2);
        #pragma unroll
        for (int ks = 0; ks < 4; ks++) {
            uint32_t a[2][4], bf[4][2];
            ldsm_x4(a[0][0], a[0][1], a[0][2], a[0][3], aOff + ks*32);
            ldsm_x4(a[1][0], a[1][1], a[1][2], a[1][3], aOff + 16*A_STRIDE_H*2 + ks*32);
            ldsm_x4(bf[0][0], bf[0][1], bf[1][0], bf[1][1], bOff + ks*32);
            ldsm_x4(bf[2][0], bf[2][1], bf[3][0], bf[3][1], bOff + 16*W_STRIDE_H*2 + ks*32);
            #pragma unroll
            for (int mt = 0; mt < 2; mt++)
                #pragma unroll
                for (int nt = 0; nt < 4; nt++)
                    mma_f16_16n8k16(acc[mt][nt], a[mt], bf[nt]);
        }
        if (c + 1 < 9) { stchunk(b ^ 1); stw(b ^ 1); }
        __syncthreads();
    }

    conv_epilogue(acc, s_bias, &es, wm, wn, wid, lane, rA, qA, y, x0, cta, out);
}

// ================= mix as mma: pair = W3 @ [p1n; p2n] (stats -> partials idx1) =================
// CTA: 128 px x 64 co, K = 128 (64 p1 + 64 p2), single-stage.
#define A5_STRIDE_H 136
#define W5_STRIDE_H 136
#define MIX_SMEM ((128*A5_STRIDE_H + 64*W5_STRIDE_H)*2)

__global__ void __launch_bounds__(256, 2)
k5_mma(float* __restrict__ out)
{
    extern __shared__ __half smh5[];
    __half* sA = smh5;                       // 128*136
    __half* sW = smh5 + 128*A5_STRIDE_H;     // 64*136
    __shared__ float s_nsc[64], s_nsh[64];
    __shared__ EpiSmem es;

    int tid = threadIdx.x, lane = tid & 31, wid = tid >> 5;
    int x0 = blockIdx.x * 128, y = blockIdx.y;
    int cta = blockIdx.y * 3 + blockIdx.x;
    int wm = wid & 3, wn = wid >> 2;
    int rA = lane >> 2, qA = lane & 3;

    if (tid < 64) { s_nsc[tid] = g_nsc[tid]; s_nsh[tid] = g_nsh[tid]; }  // idx 0
    __syncthreads();

    // stage W3 (64co x 128k half)
    {
        const uint4* ps = (const uint4*)g_w3h;
        char* wb = (char*)sW;
        #pragma unroll
        for (int r = 0; r < 4; r++) {
            int u = tid + r*256;            // 1024 units of 8 half
            int co = u >> 4, seg = u & 15;
            *(uint4*)(wb + co*272 + seg*16) = ps[u];
        }
    }
    // stage activations: k<64 = p1 = lrelu(Ag[c][y]+Bg[c][gx]); k>=64 = p2 = lrelu(nsc*bufP+nsh)
    {
        char* ab = (char*)sA;
        #pragma unroll
        for (int r = 0; r < 4; r++) {
            int e = tid + r*256;
            int px = e & 127, kg = e >> 7;
            int gx = x0 + px, cb = kg*8;
            float f[8];
            #pragma unroll
            for (int u = 0; u < 8; u++)
                f[u] = lrelu(g_Ag[(cb+u)*384 + y] + g_Bg[(cb+u)*384 + gx]);
            __half2 h0 = __floats2half2_rn(f[0], f[1]);
            __half2 h1 = __floats2half2_rn(f[2], f[3]);
            __half2 h2 = __floats2half2_rn(f[4], f[5]);
            __half2 h3 = __floats2half2_rn(f[6], f[7]);
            uint4 v; v.x = *(uint32_t*)&h0; v.y = *(uint32_t*)&h1;
            v.z = *(uint32_t*)&h2; v.w = *(uint32_t*)&h3;
            *(uint4*)(ab + px*272 + kg*16) = v;
        }
        int pix0 = y*IMG + x0;
        #pragma unroll
        for (int r = 0; r < 4; r++) {
            int e = tid + r*256;
            int px = e & 127, kg = e >> 7;
            int cb = kg*8;
            const float* p = g_bufP + cb*L2D + pix0 + px;
            float f[8];
            #pragma unroll
            for (int u = 0; u < 8; u++)
                f[u] = lrelu(p[u*L2D]*s_nsc[cb+u] + s_nsh[cb+u]);
            __half2 h0 = __floats2half2_rn(f[0], f[1]);
            __half2 h1 = __floats2half2_rn(f[2], f[3]);
            __half2 h2 = __floats2half2_rn(f[4], f[5]);
            __half2 h3 = __floats2half2_rn(f[6], f[7]);
            uint4 v; v.x = *(uint32_t*)&h0; v.y = *(uint32_t*)&h1;
            v.z = *(uint32_t*)&h2; v.w = *(uint32_t*)&h3;
            *(uint4*)(ab + px*272 + (8+kg)*16) = v;
        }
    }
    __syncthreads();

    float acc[2][4][4];
    #pragma unroll
    for (int mt = 0; mt < 2; mt++)
        #pragma unroll
        for (int nt = 0; nt < 4; nt++)
            #pragma unroll
            for (int r = 0; r < 4; r++) acc[mt][nt][r] = 0.f;

    uint32_t aBase = smem_u32(sA) + (uint32_t)(((wm*32 + (lane & 15))*A5_STRIDE_H
                    + ((lane >> 4) << 3)) * 2);
    uint32_t bBase = smem_u32(sW) + (uint32_t)(((wn*32 + (lane & 7) + ((lane >> 4) << 3))*W5_STRIDE_H
                    + (lane & 8)) * 2);

    #pragma unroll
    for (int ks = 0; ks < 8; ks++) {
        uint32_t a[2][4], bf[4][2];
        ldsm_x4(a[0][0], a[0][1], a[0][2], a[0][3], aBase + ks*32);
        ldsm_x4(a[1][0], a[1][1], a[1][2], a[1][3], aBase + 16*A5_STRIDE_H*2 + ks*32);
        ldsm_x4(bf[0][0], bf[0][1], bf[1][0], bf[1][1], bBase + ks*32);
        ldsm_x4(bf[2][0], bf[2][1], bf[3][0], bf[3][1], bBase + 16*W5_STRIDE_H*2 + ks*32);
        #pragma unroll
        for (int mt = 0; mt < 2; mt++)
            #pragma unroll
            for (int nt = 0; nt < 4; nt++)
                mma_f16_16n8k16(acc[mt][nt], a[mt], bf[nt]);
    }
    __syncthreads();

    conv_epilogue(acc, nullptr, &es, wm, wn, wid, lane, rA, qA, y, x0, cta, out);
}

// ---------------- launch ----------------
extern "C" void kernel_launch(void* const* d_in, const int* in_sizes, int n_in,
                              void* d_out, int out_size) {
    const float* x1d  = (const float*)d_in[0];
    const float* x2   = (const float*)d_in[1];
    const float* W1   = (const float*)d_in[2];
    const float* g1   = (const float*)d_in[3];
    const float* b1   = (const float*)d_in[4];
    const float* W2   = (const float*)d_in[5];
    const float* g2   = (const float*)d_in[6];
    const float* b2   = (const float*)d_in[7];
    const float* W3   = (const float*)d_in[8];
    const float* g3   = (const float*)d_in[9];
    const float* b3   = (const float*)d_in[10];
    const float* rw   = (const float*)d_in[11];
    const float* rb   = (const float*)d_in[12];
    const float* rg   = (const float*)d_in[13];
    const float* rbe  = (const float*)d_in[14];
    float* out = (float*)d_out;

    float *bP, *bR, *bX, *bT;
    __half* wh;
    cudaGetSymbolAddress((void**)&bP, g_bufP);
    cudaGetSymbolAddress((void**)&bR, g_bufR);
    cudaGetSymbolAddress((void**)&bX, g_bufX);
    cudaGetSymbolAddress((void**)&bT, g_bufT);
    cudaGetSymbolAddress((void**)&wh, g_wswh);

    cudaFuncSetAttribute(conv_mma<false>, cudaFuncAttributeMaxDynamicSharedMemorySize, CONV_SMEM);
    cudaFuncSetAttribute(conv_mma<true>,  cudaFuncAttributeMaxDynamicSharedMemorySize, CONV_SMEM);
    cudaFuncSetAttribute(k5_mma, cudaFuncAttributeMaxDynamicSharedMemorySize, MIX_SMEM);

    dim3 cgrid(3, 384);

    k_zero<<<4, 256>>>();
    k_wprep<<<1440, 256>>>(rw);
    k_w3prep<<<32, 256>>>(W3);
    k1_norm1d<<<788, 384>>>(x1d);
    k2_x2stats<<<dim3(36, 210), 256>>>(x2);
    k2b_scaleW2<<<64, 256>>>(W2);
    k3_rowcol<<<128, 384>>>(W1);
    k3b_pair1<<<64, 128>>>(g1, b1);
    k4_pair2<<<dim3(288, 2), 256>>>(x2);
    k_fin<<<1, 64>>>(0, g2, b2);
    k5_mma<<<cgrid, 256, MIX_SMEM>>>(bR);
    k_finred<<<64, 256>>>(1, g3, b3);
    k_apply4<<<9216, 256>>>((const float4*)bR, 1, nullptr, (float4*)bX);

    float* cur = bX;
    float* other = bP;
    const int DIL[5] = {1, 2, 4, 2, 1};
    for (int l = 0; l < 5; l++) {
        int D = DIL[l];
        int si0 = 2 + l*2, si1 = si0 + 1;
        conv_mma<false><<<cgrid, 256, CONV_SMEM>>>(cur, 0, wh + (l*2)*36864, D,
                                                   rb + (l*2)*64, bR);
        k_finred<<<64, 256>>>(si0, rg + (l*2)*64, rbe + (l*2)*64);
        conv_mma<true><<<cgrid, 256, CONV_SMEM>>>(bR, si0, wh + (l*2+1)*36864, D,
                                                  rb + (l*2+1)*64, bT);
        k_finred<<<64, 256>>>(si1, rg + (l*2+1)*64, rbe + (l*2+1)*64);
        float* dst = (l == 4) ? out : other;
        k_apply4<<<9216, 256>>>((const float4*)bT, si1, (const float4*)cur, (float4*)dst);
        if (l < 4) { float* tmp = cur; cur = other; other = tmp; }
    }
}

// round 14
// speedup vs baseline: 5.2354x; 1.2880x over previous
#include <cuda_runtime.h>
#include <cuda_fp16.h>
#include <cstdint>

#define L2D 147456   // 384*384
#define IMG 384
#define NPIX_INV (1.0/147456.0)

// ---------------- static scratch ----------------
__device__ float g_x1n[788*384];
__device__ float g_row[64*384];
__device__ float g_col[64*384];
__device__ float g_Ag[64*384];
__device__ float g_Bg[64*384];
__device__ float g_c2[64];
__device__ double g_x2s[210];
__device__ double g_x2q[210];
__device__ float g_nsc[16*64];
__device__ float g_nsh[16*64];

__device__ __half g_wswh[10*64*576];   // fp16 conv weights, [l2k][co][k = tap*64 + ci]
__device__ __half g_w2h[64*256];       // fp16 pair2 weights (norm-folded), [co][k], zero-padded
__device__ __half g_w3h[64*128];       // fp16 mix weights, [co][k]
__device__ float g_pS[64*1152];        // per-CTA partial sums (deterministic)
__device__ float g_pQ[64*1152];

__device__ float g_bufP[64*L2D];
__device__ float g_bufR[64*L2D];
__device__ float g_bufX[64*L2D];
__device__ float g_bufT[64*L2D];

// ---------------- helpers ----------------
__device__ __forceinline__ uint32_t smem_u32(const void* p){
    uint32_t a;
    asm("{ .reg .u64 t; cvta.to.shared.u64 t, %1; cvt.u32.u64 %0, t; }" : "=r"(a) : "l"(p));
    return a;
}
__device__ __forceinline__ void mma_f16_16n8k16(float* c, const uint32_t* a, const uint32_t* b){
    asm volatile("mma.sync.aligned.m16n8k16.row.col.f32.f16.f16.f32 "
        "{%0,%1,%2,%3}, {%4,%5,%6,%7}, {%8,%9}, {%0,%1,%2,%3};"
        : "+f"(c[0]), "+f"(c[1]), "+f"(c[2]), "+f"(c[3])
        : "r"(a[0]), "r"(a[1]), "r"(a[2]), "r"(a[3]), "r"(b[0]), "r"(b[1]));
}
__device__ __forceinline__ void ldsm_x4(uint32_t& r0, uint32_t& r1, uint32_t& r2, uint32_t& r3,
                                        uint32_t addr){
    asm volatile("ldmatrix.sync.aligned.m8n8.x4.shared.b16 {%0,%1,%2,%3}, [%4];"
        : "=r"(r0), "=r"(r1), "=r"(r2), "=r"(r3) : "r"(addr));
}

__device__ __forceinline__ void blockReduce2(float& s, float& q, float* sm) {
    __syncthreads();
    int lane = threadIdx.x & 31, w = threadIdx.x >> 5;
    #pragma unroll
    for (int o = 16; o; o >>= 1) {
        s += __shfl_down_sync(0xffffffffu, s, o);
        q += __shfl_down_sync(0xffffffffu, q, o);
    }
    if (lane == 0) { sm[2*w] = s; sm[2*w+1] = q; }
    __syncthreads();
    int nw = blockDim.x >> 5;
    if (threadIdx.x == 0) {
        float S = 0.f, Q = 0.f;
        for (int i = 0; i < nw; i++) { S += sm[2*i]; Q += sm[2*i+1]; }
        sm[0] = S; sm[1] = Q;
    }
    __syncthreads();
    s = sm[0]; q = sm[1];
}

__device__ __forceinline__ float lrelu(float v) { return v < 0.f ? 0.01f*v : v; }

// ---------------- zero stats ----------------
__global__ void k_zero() {
    int t = threadIdx.x;
    if (t < 210) { g_x2s[t] = 0.0; g_x2q[t] = 0.0; }
}

// ---------------- weight prep ----------------
__global__ void k_wprep(const float* __restrict__ rw) {
    int i = blockIdx.x*256 + threadIdx.x;
    if (i >= 10*64*64*9) return;
    int tap = i % 9; int r = i / 9;
    int ci = r & 63; r >>= 6;
    int co = r & 63; int l2k = r >> 6;
    g_wswh[(l2k*64 + co)*576 + tap*64 + ci] = __float2half(rw[i]);
}
__global__ void k_w3prep(const float* __restrict__ W3) {
    int i = blockIdx.x*256 + threadIdx.x;   // 8192
    g_w3h[i] = __float2half(W3[i]);
}

// ---------------- x_1d instance norm ----------------
__global__ void k1_norm1d(const float* __restrict__ x) {
    __shared__ float sm[32];
    int d = blockIdx.x;
    float v = x[d*384 + threadIdx.x];
    float s = v, q = v*v;
    blockReduce2(s, q, sm);
    float mu = s * (1.f/384.f);
    float var = q * (1.f/384.f) - mu*mu;
    float iv = rsqrtf(var + 1e-5f);
    g_x1n[d*384 + threadIdx.x] = (v - mu) * iv;
}

// ---------------- x_2d per-channel stats (float4) ----------------
__global__ void k2_x2stats(const float* __restrict__ x2) {
    __shared__ float sm[32];
    int c = blockIdx.y;
    const float4* p = (const float4*)(x2 + c*L2D + blockIdx.x*4096);
    float s = 0.f, q = 0.f;
    #pragma unroll
    for (int k = 0; k < 4; k++) {
        float4 v = p[threadIdx.x + k*256];
        s += v.x + v.y + v.z + v.w;
        q += v.x*v.x + v.y*v.y + v.z*v.z + v.w*v.w;
    }
    blockReduce2(s, q, sm);
    if (threadIdx.x == 0) {
        atomicAdd(&g_x2s[c], (double)s);
        atomicAdd(&g_x2q[c], (double)q);
    }
}

// ---------------- fold x2 norm into W2 -> fp16 (zero-padded K=256) ----------------
__global__ void k2b_scaleW2(const float* __restrict__ W2) {
    __shared__ float smu[210], siv[210];
    __shared__ float sm[32];
    int t = threadIdx.x, co = blockIdx.x;
    if (t < 210) {
        float mu = (float)(g_x2s[t] * NPIX_INV);
        float var = (float)(g_x2q[t] * NPIX_INV) - mu*mu;
        smu[t] = mu; siv[t] = rsqrtf(var + 1e-5f);
    }
    __syncthreads();
    float a = 0.f;
    float w = 0.f;
    if (t < 210) {
        w = W2[co*210 + t];
        a = w * smu[t] * siv[t];
    }
    g_w2h[co*256 + t] = __float2half(t < 210 ? w * siv[t] : 0.f);
    float dummy = 0.f;
    blockReduce2(a, dummy, sm);
    if (t == 0) g_c2[co] = -a;
}

// ---------------- row/col projections ----------------
__global__ void k3_rowcol(const float* __restrict__ W1) {
    int c = blockIdx.x >> 1, which = blockIdx.x & 1;
    const float* w = W1 + c*1576 + which*788;
    int l = threadIdx.x;
    float acc = 0.f;
    #pragma unroll 4
    for (int d = 0; d < 788; d++) acc += w[d] * g_x1n[d*384 + l];
    (which ? g_col : g_row)[c*384 + l] = acc;
}

// ---------------- pair1 separable stats ----------------
__global__ void k3b_pair1(const float* __restrict__ g1, const float* __restrict__ b1) {
    __shared__ float sm[32];
    int c = blockIdx.x, t = threadIdx.x;
    float sr = 0.f, qr = 0.f, sc_ = 0.f, qc = 0.f;
    for (int i = t; i < 384; i += 128) {
        float r = g_row[c*384+i]; sr += r; qr += r*r;
        float cl = g_col[c*384+i]; sc_ += cl; qc += cl*cl;
    }
    blockReduce2(sr, qr, sm);
    blockReduce2(sc_, qc, sm);
    float mur = sr*(1.f/384.f), muc = sc_*(1.f/384.f);
    float var = (qr*(1.f/384.f) - mur*mur) + (qc*(1.f/384.f) - muc*muc);
    float iv = rsqrtf(var + 1e-5f);
    float mu = mur + muc;
    float gc = g1[c], bc = b1[c];
    for (int i = t; i < 384; i += 128) {
        g_Ag[c*384+i] = gc*iv*(g_row[c*384+i] - mu) + bc;
        g_Bg[c*384+i] = gc*iv*g_col[c*384+i];
    }
}

// ---------------- finalize stats from per-CTA partials ----------------
__global__ void k_finred(int idx, const float* __restrict__ g, const float* __restrict__ b) {
    __shared__ float sm[32];
    int ch = blockIdx.x;
    float s = 0.f, q = 0.f;
    for (int i = threadIdx.x; i < 1152; i += 256) {
        s += g_pS[ch*1152 + i];
        q += g_pQ[ch*1152 + i];
    }
    blockReduce2(s, q, sm);
    if (threadIdx.x == 0) {
        float mu = s * (float)NPIX_INV;
        float var = q * (float)NPIX_INV - mu*mu;
        float iv = rsqrtf(var + 1e-5f);
        g_nsc[idx*64+ch] = g[ch]*iv;
        g_nsh[idx*64+ch] = b[ch] - g[ch]*iv*mu;
    }
}

// ---------------- normalize + leaky (+ residual), float4 ----------------
__global__ void k_apply4(const float4* __restrict__ raw, int idx,
                         const float4* __restrict__ res, float4* __restrict__ out) {
    int i = blockIdx.x*256 + threadIdx.x;
    int c = i / (L2D/4);
    float sc = g_nsc[idx*64+c], sh = g_nsh[idx*64+c];
    float4 v = raw[i];
    v.x = lrelu(v.x*sc + sh);
    v.y = lrelu(v.y*sc + sh);
    v.z = lrelu(v.z*sc + sh);
    v.w = lrelu(v.w*sc + sh);
    if (res) {
        float4 r = res[i];
        v.x += r.x; v.y += r.y; v.z += r.z; v.w += r.w;
    }
    out[i] = v;
}

// ---- shared epilogue: bias + store raw + per-channel partial stats ----
struct EpiSmem { float rs[8][4][8]; float rq[8][4][8]; };

__device__ __forceinline__ void conv_epilogue(
    float acc[2][4][4], const float* s_bias, EpiSmem* es,
    int wm, int wn, int wid, int lane, int rA, int qA,
    int y, int x0, int cta, float* __restrict__ out)
{
    float ss[4][2], qq[4][2];
    #pragma unroll
    for (int nt = 0; nt < 4; nt++) { ss[nt][0]=0.f; ss[nt][1]=0.f; qq[nt][0]=0.f; qq[nt][1]=0.f; }
    int gbase = y*IMG + x0 + wm*32;
    #pragma unroll
    for (int nt = 0; nt < 4; nt++) {
        int coA = wn*32 + nt*8 + 2*qA;
        float bA = s_bias ? s_bias[coA] : 0.f;
        float bB = s_bias ? s_bias[coA+1] : 0.f;
        #pragma unroll
        for (int mt = 0; mt < 2; mt++) {
            int px = gbase + mt*16 + rA;
            float v0 = acc[mt][nt][0] + bA;
            float v1 = acc[mt][nt][1] + bB;
            float v2 = acc[mt][nt][2] + bA;
            float v3 = acc[mt][nt][3] + bB;
            out[coA*L2D + px]         = v0;
            out[(coA+1)*L2D + px]     = v1;
            out[coA*L2D + px + 8]     = v2;
            out[(coA+1)*L2D + px + 8] = v3;
            ss[nt][0] += v0 + v2;  qq[nt][0] += v0*v0 + v2*v2;
            ss[nt][1] += v1 + v3;  qq[nt][1] += v1*v1 + v3*v3;
        }
    }
    #pragma unroll
    for (int nt = 0; nt < 4; nt++)
        #pragma unroll
        for (int e = 0; e < 2; e++) {
            float s = ss[nt][e], q = qq[nt][e];
            s += __shfl_down_sync(0xffffffffu, s, 16);
            q += __shfl_down_sync(0xffffffffu, q, 16);
            s += __shfl_down_sync(0xffffffffu, s, 8);
            q += __shfl_down_sync(0xffffffffu, q, 8);
            s += __shfl_down_sync(0xffffffffu, s, 4);
            q += __shfl_down_sync(0xffffffffu, q, 4);
            ss[nt][e] = s; qq[nt][e] = q;
        }
    if (lane < 4) {
        #pragma unroll
        for (int nt = 0; nt < 4; nt++) {
            es->rs[wid][lane][nt*2]   = ss[nt][0];  es->rq[wid][lane][nt*2]   = qq[nt][0];
            es->rs[wid][lane][nt*2+1] = ss[nt][1];  es->rq[wid][lane][nt*2+1] = qq[nt][1];
        }
    }
    __syncthreads();
    int tid = threadIdx.x;
    if (tid < 64) {
        int wn2 = tid >> 5, rem = tid & 31;
        int nt = rem >> 3, low = rem & 7, qa2 = low >> 1, e = low & 1;
        float s = 0.f, q = 0.f;
        #pragma unroll
        for (int wm2 = 0; wm2 < 4; wm2++) {
            s += es->rs[wn2*4 + wm2][qa2][nt*2 + e];
            q += es->rq[wn2*4 + wm2][qa2][nt*2 + e];
        }
        g_pS[tid*1152 + cta] = s;
        g_pQ[tid*1152 + cta] = q;
    }
}

// ================= fp16 m16n8k16 implicit-GEMM conv (ldmatrix) =================
#define A_STRIDE_H 72
#define W_STRIDE_H 72
#define CONV_SMEM ((2*128*A_STRIDE_H + 2*64*W_STRIDE_H)*2)

template<bool APPLY>
__global__ void __launch_bounds__(256, 2)
conv_mma(const float* __restrict__ in, int aidx, const __half* __restrict__ wsrc,
         int D, const float* __restrict__ bias, float* __restrict__ out)
{
    extern __shared__ __half smh[];
    __half* sA = smh;                          // 2 * 128*72 half
    __half* sW = smh + 2*128*A_STRIDE_H;       // 2 * 64*72 half
    __shared__ float s_bias[64];
    __shared__ float s_nsc[64], s_nsh[64];
    __shared__ EpiSmem es;

    int tid = threadIdx.x, lane = tid & 31, wid = tid >> 5;
    int x0 = blockIdx.x * 128, y = blockIdx.y;
    int cta = blockIdx.y * 3 + blockIdx.x;
    int wm = wid & 3, wn = wid >> 2;
    int rA = lane >> 2, qA = lane & 3;

    if (tid < 64) {
        s_bias[tid] = bias[tid];
        if (APPLY) { s_nsc[tid] = g_nsc[aidx*64 + tid]; s_nsh[tid] = g_nsh[aidx*64 + tid]; }
    }
    if (APPLY) __syncthreads();

    float acc[2][4][4];
    #pragma unroll
    for (int mt = 0; mt < 2; mt++)
        #pragma unroll
        for (int nt = 0; nt < 4; nt++)
            #pragma unroll
            for (int r = 0; r < 4; r++) acc[mt][nt][r] = 0.f;

    uint4 stg[4];
    uint4 wstg[2];

    auto ldchunk = [&](int tap) {
        int dy = (tap/3 - 1)*D, dx = (tap%3 - 1)*D;
        int gy = y + dy;
        bool gyok = ((unsigned)gy < 384u);
        const float* ip = in + gy*IMG;
        #pragma unroll
        for (int r = 0; r < 4; r++) {
            int e = tid + r*256;
            int px = e & 127, kg = e >> 7;
            int gx = x0 + px + dx;
            uint4 v = make_uint4(0u, 0u, 0u, 0u);
            if (gyok && (unsigned)gx < 384u) {
                int cb = kg*8;
                const float* p = ip + cb*L2D + gx;
                float f0 = p[0],     f1 = p[L2D],   f2 = p[2*L2D], f3 = p[3*L2D];
                float f4 = p[4*L2D], f5 = p[5*L2D], f6 = p[6*L2D], f7 = p[7*L2D];
                if (APPLY) {
                    f0 = lrelu(f0*s_nsc[cb]   + s_nsh[cb]);
                    f1 = lrelu(f1*s_nsc[cb+1] + s_nsh[cb+1]);
                    f2 = lrelu(f2*s_nsc[cb+2] + s_nsh[cb+2]);
                    f3 = lrelu(f3*s_nsc[cb+3] + s_nsh[cb+3]);
                    f4 = lrelu(f4*s_nsc[cb+4] + s_nsh[cb+4]);
                    f5 = lrelu(f5*s_nsc[cb+5] + s_nsh[cb+5]);
                    f6 = lrelu(f6*s_nsc[cb+6] + s_nsh[cb+6]);
                    f7 = lrelu(f7*s_nsc[cb+7] + s_nsh[cb+7]);
                }
                __half2 h0 = __floats2half2_rn(f0, f1);
                __half2 h1 = __floats2half2_rn(f2, f3);
                __half2 h2 = __floats2half2_rn(f4, f5);
                __half2 h3 = __floats2half2_rn(f6, f7);
                v.x = *(uint32_t*)&h0; v.y = *(uint32_t*)&h1;
                v.z = *(uint32_t*)&h2; v.w = *(uint32_t*)&h3;
            }
            stg[r] = v;
        }
    };
    auto stchunk = [&](int b) {
        char* abuf = (char*)(sA + b*128*A_STRIDE_H);
        #pragma unroll
        for (int r = 0; r < 4; r++) {
            int e = tid + r*256;
            int px = e & 127, kg = e >> 7;
            *(uint4*)(abuf + px*144 + kg*16) = stg[r];
        }
    };
    auto ldw = [&](int tap) {
        const uint4* ps = (const uint4*)(wsrc + (tid>>2)*576 + tap*64 + (tid&3)*16);
        wstg[0] = ps[0];
        wstg[1] = ps[1];
    };
    auto stw = [&](int b) {
        char* wb = (char*)(sW + b*64*W_STRIDE_H) + (tid>>2)*144 + (tid&3)*32;
        *(uint4*)wb = wstg[0];
        *((uint4*)wb + 1) = wstg[1];
    };

    ldchunk(0); ldw(0);
    stchunk(0); stw(0);
    __syncthreads();

    uint32_t aBase = smem_u32(sA) + (uint32_t)(((wm*32 + (lane & 15))*A_STRIDE_H
                    + ((lane >> 4) << 3)) * 2);
    uint32_t bBase = smem_u32(sW) + (uint32_t)(((wn*32 + (lane & 7) + ((lane >> 4) << 3))*W_STRIDE_H
                    + (lane & 8)) * 2);

    #pragma unroll 1
    for (int c = 0; c < 9; c++) {
        int b = c & 1;
        if (c + 1 < 9) { ldchunk(c + 1); ldw(c + 1); }

        uint32_t aOff = aBase + (uint32_t)(b*128*A_STRIDE_H*2);
        uint32_t bOff = bBase + (uint32_t)(b*64*W_STRIDE_H*2);
        #pragma unroll
        for (int ks = 0; ks < 4; ks++) {
            uint32_t a[2][4], bf[4][2];
            ldsm_x4(a[0][0], a[0][1], a[0][2], a[0][3], aOff + ks*32);
            ldsm_x4(a[1][0], a[1][1], a[1][2], a[1][3], aOff + 16*A_STRIDE_H*2 + ks*32);
            ldsm_x4(bf[0][0], bf[0][1], bf[1][0], bf[1][1], bOff + ks*32);
            ldsm_x4(bf[2][0], bf[2][1], bf[3][0], bf[3][1], bOff + 16*W_STRIDE_H*2 + ks*32);
            #pragma unroll
            for (int mt = 0; mt < 2; mt++)
                #pragma unroll
                for (int nt = 0; nt < 4; nt++)
                    mma_f16_16n8k16(acc[mt][nt], a[mt], bf[nt]);
        }
        if (c + 1 < 9) { stchunk(b ^ 1); stw(b ^ 1); }
        __syncthreads();
    }

    conv_epilogue(acc, s_bias, &es, wm, wn, wid, lane, rA, qA, y, x0, cta, out);
}

// ================= pair2 as mma: bufP = W2h @ x2h + c2 (stats -> partials idx0) =================
// Same structure as conv: 128px x 64co, K = 256 (210 real, zero-padded), 4 chunks of 64.
__global__ void __launch_bounds__(256, 2)
k4_mma(const float* __restrict__ x2, float* __restrict__ out)
{
    extern __shared__ __half smh4[];
    __half* sA = smh4;
    __half* sW = smh4 + 2*128*A_STRIDE_H;
    __shared__ float s_bias[64];
    __shared__ EpiSmem es;

    int tid = threadIdx.x, lane = tid & 31, wid = tid >> 5;
    int x0 = blockIdx.x * 128, y = blockIdx.y;
    int cta = blockIdx.y * 3 + blockIdx.x;
    int wm = wid & 3, wn = wid >> 2;
    int rA = lane >> 2, qA = lane & 3;

    if (tid < 64) s_bias[tid] = g_c2[tid];

    float acc[2][4][4];
    #pragma unroll
    for (int mt = 0; mt < 2; mt++)
        #pragma unroll
        for (int nt = 0; nt < 4; nt++)
            #pragma unroll
            for (int r = 0; r < 4; r++) acc[mt][nt][r] = 0.f;

    uint4 stg[4];
    uint4 wstg[2];
    int pix0 = y*IMG + x0;

    auto ldchunk = [&](int c) {
        #pragma unroll
        for (int r = 0; r < 4; r++) {
            int e = tid + r*256;
            int px = e & 127, kg = e >> 7;
            int d0 = c*64 + kg*8;
            const float* p = x2 + d0*L2D + pix0 + px;
            float f[8];
            #pragma unroll
            for (int u = 0; u < 8; u++)
                f[u] = (d0 + u < 210) ? p[u*L2D] : 0.f;
            __half2 h0 = __floats2half2_rn(f[0], f[1]);
            __half2 h1 = __floats2half2_rn(f[2], f[3]);
            __half2 h2 = __floats2half2_rn(f[4], f[5]);
            __half2 h3 = __floats2half2_rn(f[6], f[7]);
            uint4 v; v.x = *(uint32_t*)&h0; v.y = *(uint32_t*)&h1;
            v.z = *(uint32_t*)&h2; v.w = *(uint32_t*)&h3;
            stg[r] = v;
        }
    };
    auto stchunk = [&](int b) {
        char* abuf = (char*)(sA + b*128*A_STRIDE_H);
        #pragma unroll
        for (int r = 0; r < 4; r++) {
            int e = tid + r*256;
            int px = e & 127, kg = e >> 7;
            *(uint4*)(abuf + px*144 + kg*16) = stg[r];
        }
    };
    auto ldw = [&](int c) {
        const uint4* ps = (const uint4*)(g_w2h + (tid>>2)*256 + c*64 + (tid&3)*16);
        wstg[0] = ps[0];
        wstg[1] = ps[1];
    };
    auto stw = [&](int b) {
        char* wb = (char*)(sW + b*64*W_STRIDE_H) + (tid>>2)*144 + (tid&3)*32;
        *(uint4*)wb = wstg[0];
        *((uint4*)wb + 1) = wstg[1];
    };

    ldchunk(0); ldw(0);
    stchunk(0); stw(0);
    __syncthreads();

    uint32_t aBase = smem_u32(sA) + (uint32_t)(((wm*32 + (lane & 15))*A_STRIDE_H
                    + ((lane >> 4) << 3)) * 2);
    uint32_t bBase = smem_u32(sW) + (uint32_t)(((wn*32 + (lane & 7) + ((lane >> 4) << 3))*W_STRIDE_H
                    + (lane & 8)) * 2);

    #pragma unroll 1
    for (int c = 0; c < 4; c++) {
        int b = c & 1;
        if (c + 1 < 4) { ldchunk(c + 1); ldw(c + 1); }

        uint32_t aOff = aBase + (uint32_t)(b*128*A_STRIDE_H*2);
        uint32_t bOff = bBase + (uint32_t)(b*64*W_STRIDE_H*2);
        #pragma unroll
        for (int ks = 0; ks < 4; ks++) {
            uint32_t a[2][4], bf[4][2];
            ldsm_x4(a[0][0], a[0][1], a[0][2], a[0][3], aOff + ks*32);
            ldsm_x4(a[1][0], a[1][1], a[1][2], a[1][3], aOff + 16*A_STRIDE_H*2 + ks*32);
            ldsm_x4(bf[0][0], bf[0][1], bf[1][0], bf[1][1], bOff + ks*32);
            ldsm_x4(bf[2][0], bf[2][1], bf[3][0], bf[3][1], bOff + 16*W_STRIDE_H*2 + ks*32);
            #pragma unroll
            for (int mt = 0; mt < 2; mt++)
                #pragma unroll
                for (int nt = 0; nt < 4; nt++)
                    mma_f16_16n8k16(acc[mt][nt], a[mt], bf[nt]);
        }
        if (c + 1 < 4) { stchunk(b ^ 1); stw(b ^ 1); }
        __syncthreads();
    }

    conv_epilogue(acc, s_bias, &es, wm, wn, wid, lane, rA, qA, y, x0, cta, out);
}

// ================= mix as mma: pair = W3 @ [p1n; p2n] (stats -> partials idx1) =================
#define A5_STRIDE_H 136
#define W5_STRIDE_H 136
#define MIX_SMEM ((128*A5_STRIDE_H + 64*W5_STRIDE_H)*2)

__global__ void __launch_bounds__(256, 2)
k5_mma(float* __restrict__ out)
{
    extern __shared__ __half smh5[];
    __half* sA = smh5;                       // 128*136
    __half* sW = smh5 + 128*A5_STRIDE_H;     // 64*136
    __shared__ float s_nsc[64], s_nsh[64];
    __shared__ EpiSmem es;

    int tid = threadIdx.x, lane = tid & 31, wid = tid >> 5;
    int x0 = blockIdx.x * 128, y = blockIdx.y;
    int cta = blockIdx.y * 3 + blockIdx.x;
    int wm = wid & 3, wn = wid >> 2;
    int rA = lane >> 2, qA = lane & 3;

    if (tid < 64) { s_nsc[tid] = g_nsc[tid]; s_nsh[tid] = g_nsh[tid]; }  // idx 0
    __syncthreads();

    {
        const uint4* ps = (const uint4*)g_w3h;
        char* wb = (char*)sW;
        #pragma unroll
        for (int r = 0; r < 4; r++) {
            int u = tid + r*256;
            int co = u >> 4, seg = u & 15;
            *(uint4*)(wb + co*272 + seg*16) = ps[u];
        }
    }
    {
        char* ab = (char*)sA;
        #pragma unroll
        for (int r = 0; r < 4; r++) {
            int e = tid + r*256;
            int px = e & 127, kg = e >> 7;
            int gx = x0 + px, cb = kg*8;
            float f[8];
            #pragma unroll
            for (int u = 0; u < 8; u++)
                f[u] = lrelu(g_Ag[(cb+u)*384 + y] + g_Bg[(cb+u)*384 + gx]);
            __half2 h0 = __floats2half2_rn(f[0], f[1]);
            __half2 h1 = __floats2half2_rn(f[2], f[3]);
            __half2 h2 = __floats2half2_rn(f[4], f[5]);
            __half2 h3 = __floats2half2_rn(f[6], f[7]);
            uint4 v; v.x = *(uint32_t*)&h0; v.y = *(uint32_t*)&h1;
            v.z = *(uint32_t*)&h2; v.w = *(uint32_t*)&h3;
            *(uint4*)(ab + px*272 + kg*16) = v;
        }
        int pix0 = y*IMG + x0;
        #pragma unroll
        for (int r = 0; r < 4; r++) {
            int e = tid + r*256;
            int px = e & 127, kg = e >> 7;
            int cb = kg*8;
            const float* p = g_bufP + cb*L2D + pix0 + px;
            float f[8];
            #pragma unroll
            for (int u = 0; u < 8; u++)
                f[u] = lrelu(p[u*L2D]*s_nsc[cb+u] + s_nsh[cb+u]);
            __half2 h0 = __floats2half2_rn(f[0], f[1]);
            __half2 h1 = __floats2half2_rn(f[2], f[3]);
            __half2 h2 = __floats2half2_rn(f[4], f[5]);
            __half2 h3 = __floats2half2_rn(f[6], f[7]);
            uint4 v; v.x = *(uint32_t*)&h0; v.y = *(uint32_t*)&h1;
            v.z = *(uint32_t*)&h2; v.w = *(uint32_t*)&h3;
            *(uint4*)(ab + px*272 + (8+kg)*16) = v;
        }
    }
    __syncthreads();

    float acc[2][4][4];
    #pragma unroll
    for (int mt = 0; mt < 2; mt++)
        #pragma unroll
        for (int nt = 0; nt < 4; nt++)
            #pragma unroll
            for (int r = 0; r < 4; r++) acc[mt][nt][r] = 0.f;

    uint32_t aBase = smem_u32(sA) + (uint32_t)(((wm*32 + (lane & 15))*A5_STRIDE_H
                    + ((lane >> 4) << 3)) * 2);
    uint32_t bBase = smem_u32(sW) + (uint32_t)(((wn*32 + (lane & 7) + ((lane >> 4) << 3))*W5_STRIDE_H
                    + (lane & 8)) * 2);

    #pragma unroll
    for (int ks = 0; ks < 8; ks++) {
        uint32_t a[2][4], bf[4][2];
        ldsm_x4(a[0][0], a[0][1], a[0][2], a[0][3], aBase + ks*32);
        ldsm_x4(a[1][0], a[1][1], a[1][2], a[1][3], aBase + 16*A5_STRIDE_H*2 + ks*32);
        ldsm_x4(bf[0][0], bf[0][1], bf[1][0], bf[1][1], bBase + ks*32);
        ldsm_x4(bf[2][0], bf[2][1], bf[3][0], bf[3][1], bBase + 16*W5_STRIDE_H*2 + ks*32);
        #pragma unroll
        for (int mt = 0; mt < 2; mt++)
            #pragma unroll
            for (int nt = 0; nt < 4; nt++)
                mma_f16_16n8k16(acc[mt][nt], a[mt], bf[nt]);
    }
    __syncthreads();

    conv_epilogue(acc, nullptr, &es, wm, wn, wid, lane, rA, qA, y, x0, cta, out);
}

// ---------------- launch ----------------
extern "C" void kernel_launch(void* const* d_in, const int* in_sizes, int n_in,
                              void* d_out, int out_size) {
    const float* x1d  = (const float*)d_in[0];
    const float* x2   = (const float*)d_in[1];
    const float* W1   = (const float*)d_in[2];
    const float* g1   = (const float*)d_in[3];
    const float* b1   = (const float*)d_in[4];
    const float* W2   = (const float*)d_in[5];
    const float* g2   = (const float*)d_in[6];
    const float* b2   = (const float*)d_in[7];
    const float* W3   = (const float*)d_in[8];
    const float* g3   = (const float*)d_in[9];
    const float* b3   = (const float*)d_in[10];
    const float* rw   = (const float*)d_in[11];
    const float* rb   = (const float*)d_in[12];
    const float* rg   = (const float*)d_in[13];
    const float* rbe  = (const float*)d_in[14];
    float* out = (float*)d_out;

    float *bP, *bR, *bX, *bT;
    __half* wh;
    cudaGetSymbolAddress((void**)&bP, g_bufP);
    cudaGetSymbolAddress((void**)&bR, g_bufR);
    cudaGetSymbolAddress((void**)&bX, g_bufX);
    cudaGetSymbolAddress((void**)&bT, g_bufT);
    cudaGetSymbolAddress((void**)&wh, g_wswh);

    cudaFuncSetAttribute(conv_mma<false>, cudaFuncAttributeMaxDynamicSharedMemorySize, CONV_SMEM);
    cudaFuncSetAttribute(conv_mma<true>,  cudaFuncAttributeMaxDynamicSharedMemorySize, CONV_SMEM);
    cudaFuncSetAttribute(k4_mma, cudaFuncAttributeMaxDynamicSharedMemorySize, CONV_SMEM);
    cudaFuncSetAttribute(k5_mma, cudaFuncAttributeMaxDynamicSharedMemorySize, MIX_SMEM);

    dim3 cgrid(3, 384);

    k_zero<<<1, 256>>>();                                   // #1
    k2_x2stats<<<dim3(36, 210), 256>>>(x2);                 // #2
    k2b_scaleW2<<<64, 256>>>(W2);                           // #3
    k4_mma<<<cgrid, 256, CONV_SMEM>>>(x2, bP);              // #4 (ncu window)
    k_finred<<<64, 256>>>(0, g2, b2);
    k_wprep<<<1440, 256>>>(rw);
    k_w3prep<<<32, 256>>>(W3);
    k1_norm1d<<<788, 384>>>(x1d);
    k3_rowcol<<<128, 384>>>(W1);
    k3b_pair1<<<64, 128>>>(g1, b1);
    k5_mma<<<cgrid, 256, MIX_SMEM>>>(bR);
    k_finred<<<64, 256>>>(1, g3, b3);
    k_apply4<<<9216, 256>>>((const float4*)bR, 1, nullptr, (float4*)bX);

    float* cur = bX;
    float* other = bP;
    const int DIL[5] = {1, 2, 4, 2, 1};
    for (int l = 0; l < 5; l++) {
        int D = DIL[l];
        int si0 = 2 + l*2, si1 = si0 + 1;
        conv_mma<false><<<cgrid, 256, CONV_SMEM>>>(cur, 0, wh + (l*2)*36864, D,
                                                   rb + (l*2)*64, bR);
        k_finred<<<64, 256>>>(si0, rg + (l*2)*64, rbe + (l*2)*64);
        conv_mma<true><<<cgrid, 256, CONV_SMEM>>>(bR, si0, wh + (l*2+1)*36864, D,
                                                  rb + (l*2+1)*64, bT);
        k_finred<<<64, 256>>>(si1, rg + (l*2+1)*64, rbe + (l*2+1)*64);
        float* dst = (l == 4) ? out : other;
        k_apply4<<<9216, 256>>>((const float4*)bT, si1, (const float4*)cur, (float4*)dst);
        if (l < 4) { float* tmp = cur; cur = other; other = tmp; }
    }
}